// round 1
// baseline (speedup 1.0000x reference)
#include <cuda_runtime.h>
#include <math.h>

#define NN 50000
#define NE 800000
#define NET (NE + NN)       // edges + self loops = 850000
#define HC 256              // H*C
#define NH 4
#define CC 64

// ---------------- scratch (static device globals; no allocs) ----------------
__device__ __align__(16) float g_h[NN * HC];     // transformed features (per layer)
__device__ __align__(16) float g_x1[NN * HC];    // layer-0 activated output
__device__ __align__(16) float g_acc[NN * HC];   // scatter accumulator
__device__ __align__(16) float g_w[(size_t)NET * NH];  // per-edge exp weights
__device__ __align__(16) float g_asrc[NN * NH];
__device__ __align__(16) float g_adst[NN * NH];
__device__ __align__(16) float g_s[NN * NH];     // softmax denominators
__device__ int g_is64;

// ---------------- utility ----------------
__global__ void zero_k(float* p, int n) {
    int i = blockIdx.x * blockDim.x + threadIdx.x;
    if (i < n) p[i] = 0.0f;
}

// Detect whether edge_index is int64 (high 32-bit words of first 64 values are 0)
__global__ void detect_k(const int* ei32) {
    if (threadIdx.x == 0 && blockIdx.x == 0) {
        int ok = 1;
        #pragma unroll
        for (int k = 0; k < 64; k++)
            if (ei32[2 * k + 1] != 0) ok = 0;
        g_is64 = ok;
    }
}

__device__ __forceinline__ void edge_sd(const void* ei, int e, int& s, int& d) {
    if (e >= NE) { s = d = e - NE; return; }
    if (g_is64) {
        const long long* p = (const long long*)ei;
        s = (int)p[e];
        d = (int)p[NE + e];
    } else {
        const int* p = (const int*)ei;
        s = p[e];
        d = p[NE + e];
    }
}

// ---------------- GEMM: C[M,Nc] = A[M,K] @ B[K,Nc] (+bias) ----------------
// BM=128, BN=64, BK=16, 256 threads, 8x4 per-thread tile.
// FMAX: A-element = max(A[m,k], A2[m,k] + ab[k])  (fused JK-max + bias)
template <bool FMAX, bool BIAS>
__global__ __launch_bounds__(256) void gemm_k(
    const float* __restrict__ A, const float* __restrict__ A2,
    const float* __restrict__ ab, const float* __restrict__ B,
    const float* __restrict__ bias, float* __restrict__ C,
    int M, int K, int Nc)
{
    __shared__ float As[16][132];
    __shared__ float Bs[16][64];
    const int tid = threadIdx.x;
    const int m0 = blockIdx.y * 128;
    const int n0 = blockIdx.x * 64;
    const int ty = tid >> 4;        // 0..15 -> M (x8)
    const int tx = tid & 15;        // 0..15 -> N (x4)

    float acc[8][4];
    #pragma unroll
    for (int i = 0; i < 8; i++)
        #pragma unroll
        for (int j = 0; j < 4; j++) acc[i][j] = 0.0f;

    for (int kt = 0; kt < K; kt += 16) {
        // load A tile (128x16) transposed into As[k][m]
        #pragma unroll
        for (int q0 = 0; q0 < 2; q0++) {
            int q = tid + q0 * 256;
            int r = q >> 2;
            int kb = (q & 3) * 4;
            int row = m0 + r;
            float4 v = make_float4(0.f, 0.f, 0.f, 0.f);
            if (row < M) {
                v = *(const float4*)(A + (size_t)row * K + kt + kb);
                if (FMAX) {
                    float4 v2 = *(const float4*)(A2 + (size_t)row * K + kt + kb);
                    float4 bb = *(const float4*)(ab + kt + kb);
                    v.x = fmaxf(v.x, v2.x + bb.x);
                    v.y = fmaxf(v.y, v2.y + bb.y);
                    v.z = fmaxf(v.z, v2.z + bb.z);
                    v.w = fmaxf(v.w, v2.w + bb.w);
                }
            }
            As[kb + 0][r] = v.x;
            As[kb + 1][r] = v.y;
            As[kb + 2][r] = v.z;
            As[kb + 3][r] = v.w;
        }
        // load B tile (16x64)
        {
            int r = tid >> 4;
            int n = (tid & 15) * 4;
            *(float4*)&Bs[r][n] = *(const float4*)(B + (size_t)(kt + r) * Nc + n0 + n);
        }
        __syncthreads();

        #pragma unroll
        for (int kk = 0; kk < 16; kk++) {
            float4 a0 = *(const float4*)&As[kk][ty * 8];
            float4 a1 = *(const float4*)&As[kk][ty * 8 + 4];
            float4 bv = *(const float4*)&Bs[kk][tx * 4];
            float a[8] = {a0.x, a0.y, a0.z, a0.w, a1.x, a1.y, a1.z, a1.w};
            float b[4] = {bv.x, bv.y, bv.z, bv.w};
            #pragma unroll
            for (int i = 0; i < 8; i++)
                #pragma unroll
                for (int j = 0; j < 4; j++)
                    acc[i][j] = fmaf(a[i], b[j], acc[i][j]);
        }
        __syncthreads();
    }

    float4 bv = make_float4(0.f, 0.f, 0.f, 0.f);
    if (BIAS) bv = *(const float4*)(bias + n0 + tx * 4);
    #pragma unroll
    for (int i = 0; i < 8; i++) {
        int row = m0 + ty * 8 + i;
        if (row < M) {
            float4 v = make_float4(acc[i][0] + bv.x, acc[i][1] + bv.y,
                                   acc[i][2] + bv.z, acc[i][3] + bv.w);
            *(float4*)(C + (size_t)row * Nc + n0 + tx * 4) = v;
        }
    }
}

// ---------------- per-node attention coefficients ----------------
// one warp per (node, head): asrc[n,h] = sum_c h[n,h,c]*a_src[h,c]
__global__ void alpha_k(const float* __restrict__ h,
                        const float* __restrict__ aS,
                        const float* __restrict__ aD)
{
    int gt = blockIdx.x * blockDim.x + threadIdx.x;
    int w = gt >> 5;
    int lane = gt & 31;
    if (w >= NN * NH) return;
    int node = w >> 2, head = w & 3;
    const float* hp = h + (size_t)node * HC + head * CC;
    float h0 = hp[lane], h1 = hp[lane + 32];
    float s = h0 * aS[head * CC + lane] + h1 * aS[head * CC + lane + 32];
    float d = h0 * aD[head * CC + lane] + h1 * aD[head * CC + lane + 32];
    #pragma unroll
    for (int o = 16; o; o >>= 1) {
        s += __shfl_xor_sync(0xffffffffu, s, o);
        d += __shfl_xor_sync(0xffffffffu, d, o);
    }
    if (lane == 0) { g_asrc[w] = s; g_adst[w] = d; }
}

// ---------------- edge weights: w = exp(leaky_relu(asrc[s]+adst[d])), s-sum ----------------
__device__ __forceinline__ float lrexp(float t) {
    t = t > 0.f ? t : 0.2f * t;
    return expf(t);
}

__global__ void edgew_k(const void* __restrict__ ei) {
    int e = blockIdx.x * blockDim.x + threadIdx.x;
    if (e >= NET) return;
    int s, d;
    edge_sd(ei, e, s, d);
    float4 av = *(const float4*)(g_asrc + s * 4);
    float4 dv = *(const float4*)(g_adst + d * 4);
    float4 w;
    w.x = lrexp(av.x + dv.x);
    w.y = lrexp(av.y + dv.y);
    w.z = lrexp(av.z + dv.z);
    w.w = lrexp(av.w + dv.w);
    *(float4*)(g_w + (size_t)e * 4) = w;
    float* sp = g_s + d * 4;
    atomicAdd(sp + 0, w.x);
    atomicAdd(sp + 1, w.y);
    atomicAdd(sp + 2, w.z);
    atomicAdd(sp + 3, w.w);
}

// ---------------- message scatter: acc[d] += h[s] * alpha ----------------
// 64 threads per edge; thread c handles channel c of all 4 heads.
__global__ __launch_bounds__(256) void scatter_k(const void* __restrict__ ei,
                                                 const float* __restrict__ h)
{
    int idx = blockIdx.x * 256 + threadIdx.x;
    int e = idx >> 6;
    if (e >= NET) return;
    int c = idx & 63;
    int s, d;
    edge_sd(ei, e, s, d);
    float4 wv = *(const float4*)(g_w + (size_t)e * 4);
    float4 sv = *(const float4*)(g_s + d * 4);
    float a0 = wv.x / (sv.x + 1e-16f);
    float a1 = wv.y / (sv.y + 1e-16f);
    float a2 = wv.z / (sv.z + 1e-16f);
    float a3 = wv.w / (sv.w + 1e-16f);
    const float* hp = h + (size_t)s * HC;
    float* op = g_acc + (size_t)d * HC;
    atomicAdd(op + c,        hp[c]        * a0);
    atomicAdd(op + 64 + c,   hp[64 + c]   * a1);
    atomicAdd(op + 128 + c,  hp[128 + c]  * a2);
    atomicAdd(op + 192 + c,  hp[192 + c]  * a3);
}

// ---------------- bias + BatchNorm(eval) + ELU ----------------
__global__ void act_k(const float* __restrict__ b0,
                      const float* __restrict__ gamma,
                      const float* __restrict__ beta)
{
    int i = blockIdx.x * blockDim.x + threadIdx.x;
    if (i >= NN * HC) return;
    int j = i & 255;
    float sc = gamma[j] * rsqrtf(1.0f + 1e-5f);
    float v = (g_acc[i] + b0[j]) * sc + beta[j];
    g_x1[i] = v > 0.f ? v : expm1f(v);
}

// ---------------- launch ----------------
extern "C" void kernel_launch(void* const* d_in, const int* in_sizes, int n_in,
                              void* d_out, int out_size)
{
    const float* x      = (const float*)d_in[0];
    const void*  ei     = d_in[1];
    const float* W0     = (const float*)d_in[2];
    const float* as0    = (const float*)d_in[3];
    const float* ad0    = (const float*)d_in[4];
    const float* b0     = (const float*)d_in[5];
    const float* gamma0 = (const float*)d_in[6];
    const float* beta0  = (const float*)d_in[7];
    const float* W1     = (const float*)d_in[8];
    const float* as1    = (const float*)d_in[9];
    const float* ad1    = (const float*)d_in[10];
    const float* b1     = (const float*)d_in[11];
    const float* Wf     = (const float*)d_in[12];
    const float* bf     = (const float*)d_in[13];
    float* out = (float*)d_out;

    float *h, *x1, *acc, *sbuf;
    cudaGetSymbolAddress((void**)&h,    g_h);
    cudaGetSymbolAddress((void**)&x1,   g_x1);
    cudaGetSymbolAddress((void**)&acc,  g_acc);
    cudaGetSymbolAddress((void**)&sbuf, g_s);

    const int mb = (NN + 127) / 128;  // 391
    const int zb_big   = (NN * HC + 255) / 256;
    const int zb_small = (NN * NH + 255) / 256;
    const int ab       = (NN * NH * 32 + 255) / 256;
    const int eb       = (NET + 255) / 256;
    const int sb       = ((size_t)NET * 64 + 255) / 256;

    detect_k<<<1, 32>>>((const int*)ei);

    // ---- layer 0 ----
    zero_k<<<zb_big, 256>>>(acc, NN * HC);
    zero_k<<<zb_small, 256>>>(sbuf, NN * NH);
    gemm_k<false, false><<<dim3(HC / 64, mb), 256>>>(x, nullptr, nullptr, W0, nullptr, h, NN, 128, HC);
    alpha_k<<<ab, 256>>>(h, as0, ad0);
    edgew_k<<<eb, 256>>>(ei);
    scatter_k<<<sb, 256>>>(ei, h);
    act_k<<<zb_big, 256>>>(b0, gamma0, beta0);

    // ---- layer 1 ----
    zero_k<<<zb_big, 256>>>(acc, NN * HC);
    zero_k<<<zb_small, 256>>>(sbuf, NN * NH);
    gemm_k<false, false><<<dim3(HC / 64, mb), 256>>>(x1, nullptr, nullptr, W1, nullptr, h, NN, HC, HC);
    alpha_k<<<ab, 256>>>(h, as1, ad1);
    edgew_k<<<eb, 256>>>(ei);
    scatter_k<<<sb, 256>>>(ei, h);

    // ---- JK-max + final projection: out = max(x1, acc + b1) @ Wf + bf ----
    gemm_k<true, true><<<dim3(1, mb), 256>>>(x1, acc, b1, Wf, bf, out, NN, HC, 64);
}

// round 2
// speedup vs baseline: 1.8522x; 1.8522x over previous
#include <cuda_runtime.h>
#include <math.h>

#define NN 50000
#define NE 800000
#define NET (NE + NN)       // edges + self loops = 850000
#define HC 256              // H*C
#define NH 4
#define CC 64
#define NB_SCAN 196         // ceil(NN/256)

// ---------------- scratch (static device globals; no allocs) ----------------
__device__ __align__(16) float g_h[NN * HC];      // transformed features (per layer)
__device__ __align__(16) float g_x1[NN * HC];     // layer-0 activated output
__device__ __align__(16) float g_acc[NN * HC];    // layer-1 aggregation output
__device__ __align__(16) float g_w[(size_t)NET * NH];  // per-edge exp weights
__device__ __align__(16) float g_asrc[NN * NH];
__device__ __align__(16) float g_adst[NN * NH];
__device__ int g_deg[NN];
__device__ int g_off[NN + 1];
__device__ int g_cur[NN];
__device__ int g_part[NB_SCAN];
__device__ __align__(8) int2 g_adj[NET];          // (src, edge-id) grouped by dst
__device__ int g_is64;

// ---------------- utility ----------------
__global__ void zeroi_k(int* p, int n) {
    int i = blockIdx.x * blockDim.x + threadIdx.x;
    if (i < n) p[i] = 0;
}

// Detect whether edge_index is int64 (high 32-bit words of first 64 values are 0)
__global__ void detect_k(const int* ei32) {
    if (threadIdx.x == 0 && blockIdx.x == 0) {
        int ok = 1;
        #pragma unroll
        for (int k = 0; k < 64; k++)
            if (ei32[2 * k + 1] != 0) ok = 0;
        g_is64 = ok;
    }
}

__device__ __forceinline__ void edge_sd(const void* ei, int e, int& s, int& d) {
    if (e >= NE) { s = d = e - NE; return; }
    if (g_is64) {
        const long long* p = (const long long*)ei;
        s = (int)p[e];
        d = (int)p[NE + e];
    } else {
        const int* p = (const int*)ei;
        s = p[e];
        d = p[NE + e];
    }
}

// ---------------- CSR build ----------------
__global__ void hist_k(const void* __restrict__ ei) {
    int e = blockIdx.x * blockDim.x + threadIdx.x;
    if (e >= NET) return;
    int s, d;
    edge_sd(ei, e, s, d);
    atomicAdd(&g_deg[d], 1);
}

__global__ void scan1_k() {   // per-block sums of deg
    __shared__ int sh[256];
    int i = blockIdx.x * 256 + threadIdx.x;
    int v = (i < NN) ? g_deg[i] : 0;
    sh[threadIdx.x] = v; __syncthreads();
    for (int o = 128; o; o >>= 1) {
        if (threadIdx.x < o) sh[threadIdx.x] += sh[threadIdx.x + o];
        __syncthreads();
    }
    if (threadIdx.x == 0) g_part[blockIdx.x] = sh[0];
}

__global__ void scan2_k() {   // exclusive scan of NB_SCAN partials (1 block)
    __shared__ int sh[256];
    int t = threadIdx.x;
    int v = (t < NB_SCAN) ? g_part[t] : 0;
    sh[t] = v; __syncthreads();
    for (int o = 1; o < 256; o <<= 1) {
        int x = (t >= o) ? sh[t - o] : 0;
        __syncthreads();
        sh[t] += x;
        __syncthreads();
    }
    if (t < NB_SCAN) g_part[t] = sh[t] - v;   // exclusive
}

__global__ void scan3_k() {   // per-block exclusive scan + offset -> off, cur
    __shared__ int sh[256];
    int t = threadIdx.x;
    int i = blockIdx.x * 256 + t;
    int v = (i < NN) ? g_deg[i] : 0;
    sh[t] = v; __syncthreads();
    for (int o = 1; o < 256; o <<= 1) {
        int x = (t >= o) ? sh[t - o] : 0;
        __syncthreads();
        sh[t] += x;
        __syncthreads();
    }
    if (i < NN) {
        int off = g_part[blockIdx.x] + sh[t] - v;
        g_off[i] = off;
        g_cur[i] = off;
        if (i == NN - 1) g_off[NN] = off + v;
    }
}

__global__ void fill_k(const void* __restrict__ ei) {
    int e = blockIdx.x * blockDim.x + threadIdx.x;
    if (e >= NET) return;
    int s, d;
    edge_sd(ei, e, s, d);
    int p = atomicAdd(&g_cur[d], 1);
    g_adj[p] = make_int2(s, e);
}

// ---------------- GEMM: C[M,Nc] = A[M,K] @ B[K,Nc] (+bias) ----------------
template <bool FMAX, bool BIAS>
__global__ __launch_bounds__(256) void gemm_k(
    const float* __restrict__ A, const float* __restrict__ A2,
    const float* __restrict__ ab, const float* __restrict__ B,
    const float* __restrict__ bias, float* __restrict__ C,
    int M, int K, int Nc)
{
    __shared__ float As[16][132];
    __shared__ float Bs[16][64];
    const int tid = threadIdx.x;
    const int m0 = blockIdx.y * 128;
    const int n0 = blockIdx.x * 64;
    const int ty = tid >> 4;
    const int tx = tid & 15;

    float acc[8][4];
    #pragma unroll
    for (int i = 0; i < 8; i++)
        #pragma unroll
        for (int j = 0; j < 4; j++) acc[i][j] = 0.0f;

    for (int kt = 0; kt < K; kt += 16) {
        #pragma unroll
        for (int q0 = 0; q0 < 2; q0++) {
            int q = tid + q0 * 256;
            int r = q >> 2;
            int kb = (q & 3) * 4;
            int row = m0 + r;
            float4 v = make_float4(0.f, 0.f, 0.f, 0.f);
            if (row < M) {
                v = *(const float4*)(A + (size_t)row * K + kt + kb);
                if (FMAX) {
                    float4 v2 = *(const float4*)(A2 + (size_t)row * K + kt + kb);
                    float4 bb = *(const float4*)(ab + kt + kb);
                    v.x = fmaxf(v.x, v2.x + bb.x);
                    v.y = fmaxf(v.y, v2.y + bb.y);
                    v.z = fmaxf(v.z, v2.z + bb.z);
                    v.w = fmaxf(v.w, v2.w + bb.w);
                }
            }
            As[kb + 0][r] = v.x;
            As[kb + 1][r] = v.y;
            As[kb + 2][r] = v.z;
            As[kb + 3][r] = v.w;
        }
        {
            int r = tid >> 4;
            int n = (tid & 15) * 4;
            *(float4*)&Bs[r][n] = *(const float4*)(B + (size_t)(kt + r) * Nc + n0 + n);
        }
        __syncthreads();

        #pragma unroll
        for (int kk = 0; kk < 16; kk++) {
            float4 a0 = *(const float4*)&As[kk][ty * 8];
            float4 a1 = *(const float4*)&As[kk][ty * 8 + 4];
            float4 bv = *(const float4*)&Bs[kk][tx * 4];
            float a[8] = {a0.x, a0.y, a0.z, a0.w, a1.x, a1.y, a1.z, a1.w};
            float b[4] = {bv.x, bv.y, bv.z, bv.w};
            #pragma unroll
            for (int i = 0; i < 8; i++)
                #pragma unroll
                for (int j = 0; j < 4; j++)
                    acc[i][j] = fmaf(a[i], b[j], acc[i][j]);
        }
        __syncthreads();
    }

    float4 bv = make_float4(0.f, 0.f, 0.f, 0.f);
    if (BIAS) bv = *(const float4*)(bias + n0 + tx * 4);
    #pragma unroll
    for (int i = 0; i < 8; i++) {
        int row = m0 + ty * 8 + i;
        if (row < M) {
            float4 v = make_float4(acc[i][0] + bv.x, acc[i][1] + bv.y,
                                   acc[i][2] + bv.z, acc[i][3] + bv.w);
            *(float4*)(C + (size_t)row * Nc + n0 + tx * 4) = v;
        }
    }
}

// ---------------- per-node attention coefficients ----------------
__global__ void alpha_k(const float* __restrict__ h,
                        const float* __restrict__ aS,
                        const float* __restrict__ aD)
{
    int gt = blockIdx.x * blockDim.x + threadIdx.x;
    int w = gt >> 5;
    int lane = gt & 31;
    if (w >= NN * NH) return;
    int node = w >> 2, head = w & 3;
    const float* hp = h + (size_t)node * HC + head * CC;
    float h0 = hp[lane], h1 = hp[lane + 32];
    float s = h0 * aS[head * CC + lane] + h1 * aS[head * CC + lane + 32];
    float d = h0 * aD[head * CC + lane] + h1 * aD[head * CC + lane + 32];
    #pragma unroll
    for (int o = 16; o; o >>= 1) {
        s += __shfl_xor_sync(0xffffffffu, s, o);
        d += __shfl_xor_sync(0xffffffffu, d, o);
    }
    if (lane == 0) { g_asrc[w] = s; g_adst[w] = d; }
}

// ---------------- edge weights: w = exp(leaky_relu(asrc[s]+adst[d])) ----------------
__device__ __forceinline__ float lrexp(float t) {
    t = t > 0.f ? t : 0.2f * t;
    return expf(t);
}

__global__ void edgew_k(const void* __restrict__ ei) {
    int e = blockIdx.x * blockDim.x + threadIdx.x;
    if (e >= NET) return;
    int s, d;
    edge_sd(ei, e, s, d);
    float4 av = *(const float4*)(g_asrc + s * 4);
    float4 dv = *(const float4*)(g_adst + d * 4);
    float4 w;
    w.x = lrexp(av.x + dv.x);
    w.y = lrexp(av.y + dv.y);
    w.z = lrexp(av.z + dv.z);
    w.w = lrexp(av.w + dv.w);
    *(float4*)(g_w + (size_t)e * 4) = w;
}

// ---------------- CSR gather: out[d] = sum_e w[e]*h[src[e]] / sum_e w[e] ----------------
// 64 threads per node (thread c = channel c of all 4 heads); 4 nodes per block.
// ACT=true: apply bias + BatchNorm(eval) + ELU (layer 0 epilogue).
template <bool ACT>
__global__ __launch_bounds__(256) void gather_k(
    const float* __restrict__ h, float* __restrict__ out,
    const float* __restrict__ b0,
    const float* __restrict__ gamma,
    const float* __restrict__ beta)
{
    int node = blockIdx.x * 4 + (threadIdx.x >> 6);
    int c = threadIdx.x & 63;
    if (node >= NN) return;
    int p = g_off[node];
    const int end = g_off[node + 1];

    float a0 = 0.f, a1 = 0.f, a2 = 0.f, a3 = 0.f;
    float ws0 = 0.f, ws1 = 0.f, ws2 = 0.f, ws3 = 0.f;

    int2 ad = (p < end) ? g_adj[p] : make_int2(0, 0);
    for (; p < end; p++) {
        int2 nx = (p + 1 < end) ? g_adj[p + 1] : ad;
        float4 w = *(const float4*)(g_w + (size_t)ad.x * 0 + (size_t)ad.y * 4);
        const float* hp = h + (size_t)ad.x * HC;
        a0 = fmaf(w.x, hp[c],        a0);
        a1 = fmaf(w.y, hp[64 + c],   a1);
        a2 = fmaf(w.z, hp[128 + c],  a2);
        a3 = fmaf(w.w, hp[192 + c],  a3);
        ws0 += w.x; ws1 += w.y; ws2 += w.z; ws3 += w.w;
        ad = nx;
    }
    a0 /= (ws0 + 1e-16f);
    a1 /= (ws1 + 1e-16f);
    a2 /= (ws2 + 1e-16f);
    a3 /= (ws3 + 1e-16f);

    float* op = out + (size_t)node * HC;
    if (ACT) {
        const float r = rsqrtf(1.0f + 1e-5f);
        #pragma unroll
        for (int hh = 0; hh < 4; hh++) {
            float a = (hh == 0) ? a0 : (hh == 1) ? a1 : (hh == 2) ? a2 : a3;
            int j = hh * 64 + c;
            float v = (a + b0[j]) * (gamma[j] * r) + beta[j];
            op[j] = v > 0.f ? v : expm1f(v);
        }
    } else {
        op[c]       = a0;
        op[64 + c]  = a1;
        op[128 + c] = a2;
        op[192 + c] = a3;
    }
}

// ---------------- launch ----------------
extern "C" void kernel_launch(void* const* d_in, const int* in_sizes, int n_in,
                              void* d_out, int out_size)
{
    const float* x      = (const float*)d_in[0];
    const void*  ei     = d_in[1];
    const float* W0     = (const float*)d_in[2];
    const float* as0    = (const float*)d_in[3];
    const float* ad0    = (const float*)d_in[4];
    const float* b0     = (const float*)d_in[5];
    const float* gamma0 = (const float*)d_in[6];
    const float* beta0  = (const float*)d_in[7];
    const float* W1     = (const float*)d_in[8];
    const float* as1    = (const float*)d_in[9];
    const float* ad1    = (const float*)d_in[10];
    const float* b1     = (const float*)d_in[11];
    const float* Wf     = (const float*)d_in[12];
    const float* bf     = (const float*)d_in[13];
    float* out = (float*)d_out;

    float *h, *x1, *acc;
    int* deg;
    cudaGetSymbolAddress((void**)&h,   g_h);
    cudaGetSymbolAddress((void**)&x1,  g_x1);
    cudaGetSymbolAddress((void**)&acc, g_acc);
    cudaGetSymbolAddress((void**)&deg, g_deg);

    const int mb = (NN + 127) / 128;
    const int ab = (NN * NH * 32 + 255) / 256;
    const int eb = (NET + 255) / 256;
    const int gb = (NN + 3) / 4;

    detect_k<<<1, 32>>>((const int*)ei);

    // ---- CSR build (shared by both layers) ----
    zeroi_k<<<(NN + 255) / 256, 256>>>(deg, NN);
    hist_k<<<eb, 256>>>(ei);
    scan1_k<<<NB_SCAN, 256>>>();
    scan2_k<<<1, 256>>>();
    scan3_k<<<NB_SCAN, 256>>>();
    fill_k<<<eb, 256>>>(ei);

    // ---- layer 0 ----
    gemm_k<false, false><<<dim3(HC / 64, mb), 256>>>(x, nullptr, nullptr, W0, nullptr, h, NN, 128, HC);
    alpha_k<<<ab, 256>>>(h, as0, ad0);
    edgew_k<<<eb, 256>>>(ei);
    gather_k<true><<<gb, 256>>>(h, x1, b0, gamma0, beta0);

    // ---- layer 1 ----
    gemm_k<false, false><<<dim3(HC / 64, mb), 256>>>(x1, nullptr, nullptr, W1, nullptr, h, NN, HC, HC);
    alpha_k<<<ab, 256>>>(h, as1, ad1);
    edgew_k<<<eb, 256>>>(ei);
    gather_k<false><<<gb, 256>>>(h, acc, nullptr, nullptr, nullptr);

    // ---- JK-max + final projection: out = max(x1, acc + b1) @ Wf + bf ----
    gemm_k<true, true><<<dim3(1, mb), 256>>>(x1, acc, b1, Wf, bf, out, NN, HC, 64);
}

// round 3
// speedup vs baseline: 2.3536x; 1.2707x over previous
#include <cuda_runtime.h>
#include <math.h>

#define NN 50000
#define NE 800000
#define NET (NE + NN)       // edges + self loops = 850000
#define HC 256              // H*C
#define NH 4
#define CC 64
#define NB_SCAN 196         // ceil(NN/256)

// ---------------- scratch (static device globals; no allocs) ----------------
__device__ __align__(16) float g_h[NN * HC];      // transformed features (per layer)
__device__ __align__(16) float g_x1[NN * HC];     // layer-0 activated output
__device__ __align__(16) float g_acc[NN * HC];    // layer-1 aggregation output
__device__ __align__(16) float g_asrc[NN * NH];
__device__ __align__(16) float g_adst[NN * NH];
__device__ int g_deg[NN];
__device__ int g_off[NN + 1];
__device__ int g_cur[NN];
__device__ int g_part[NB_SCAN];
__device__ int g_adj[NET];                        // src ids grouped by dst
__device__ int g_is64;

// ---------------- utility ----------------
__global__ void zeroi_k(int* p, int n) {
    int i = blockIdx.x * blockDim.x + threadIdx.x;
    if (i < n) p[i] = 0;
}

// Detect whether edge_index is int64 (high 32-bit words of first 64 values are 0)
__global__ void detect_k(const int* ei32) {
    if (threadIdx.x == 0 && blockIdx.x == 0) {
        int ok = 1;
        #pragma unroll
        for (int k = 0; k < 64; k++)
            if (ei32[2 * k + 1] != 0) ok = 0;
        g_is64 = ok;
    }
}

__device__ __forceinline__ void edge_sd(const void* ei, int e, int& s, int& d) {
    if (e >= NE) { s = d = e - NE; return; }
    if (g_is64) {
        const long long* p = (const long long*)ei;
        s = (int)p[e];
        d = (int)p[NE + e];
    } else {
        const int* p = (const int*)ei;
        s = p[e];
        d = p[NE + e];
    }
}

// ---------------- CSR build ----------------
__global__ void hist_k(const void* __restrict__ ei) {
    int e = blockIdx.x * blockDim.x + threadIdx.x;
    if (e >= NET) return;
    int s, d;
    edge_sd(ei, e, s, d);
    atomicAdd(&g_deg[d], 1);
}

__global__ void scan1_k() {   // per-block sums of deg
    __shared__ int sh[256];
    int i = blockIdx.x * 256 + threadIdx.x;
    int v = (i < NN) ? g_deg[i] : 0;
    sh[threadIdx.x] = v; __syncthreads();
    for (int o = 128; o; o >>= 1) {
        if (threadIdx.x < o) sh[threadIdx.x] += sh[threadIdx.x + o];
        __syncthreads();
    }
    if (threadIdx.x == 0) g_part[blockIdx.x] = sh[0];
}

__global__ void scan2_k() {   // exclusive scan of NB_SCAN partials (1 block)
    __shared__ int sh[256];
    int t = threadIdx.x;
    int v = (t < NB_SCAN) ? g_part[t] : 0;
    sh[t] = v; __syncthreads();
    for (int o = 1; o < 256; o <<= 1) {
        int x = (t >= o) ? sh[t - o] : 0;
        __syncthreads();
        sh[t] += x;
        __syncthreads();
    }
    if (t < NB_SCAN) g_part[t] = sh[t] - v;   // exclusive
}

__global__ void scan3_k() {   // per-block exclusive scan + offset -> off, cur
    __shared__ int sh[256];
    int t = threadIdx.x;
    int i = blockIdx.x * 256 + t;
    int v = (i < NN) ? g_deg[i] : 0;
    sh[t] = v; __syncthreads();
    for (int o = 1; o < 256; o <<= 1) {
        int x = (t >= o) ? sh[t - o] : 0;
        __syncthreads();
        sh[t] += x;
        __syncthreads();
    }
    if (i < NN) {
        int off = g_part[blockIdx.x] + sh[t] - v;
        g_off[i] = off;
        g_cur[i] = off;
        if (i == NN - 1) g_off[NN] = off + v;
    }
}

__global__ void fill_k(const void* __restrict__ ei) {
    int e = blockIdx.x * blockDim.x + threadIdx.x;
    if (e >= NET) return;
    int s, d;
    edge_sd(ei, e, s, d);
    int p = atomicAdd(&g_cur[d], 1);
    g_adj[p] = s;
}

// ---------------- GEMM: C[M,Nc] = A[M,K] @ B[K,Nc] (+bias) ----------------
// ALPHA: also compute per-row attention dots with aS/aD (one head per block col).
// FMAX: A-element = max(A[m,k], A2[m,k] + ab[k])  (fused JK-max + bias)
template <bool ALPHA, bool FMAX, bool BIAS>
__global__ __launch_bounds__(256) void gemm_k(
    const float* __restrict__ A, const float* __restrict__ A2,
    const float* __restrict__ ab, const float* __restrict__ B,
    const float* __restrict__ bias,
    const float* __restrict__ aS, const float* __restrict__ aD,
    float* __restrict__ C,
    int M, int K, int Nc)
{
    __shared__ float As[16][132];
    __shared__ float Bs[16][64];
    const int tid = threadIdx.x;
    const int m0 = blockIdx.y * 128;
    const int n0 = blockIdx.x * 64;
    const int ty = tid >> 4;
    const int tx = tid & 15;

    float acc[8][4];
    #pragma unroll
    for (int i = 0; i < 8; i++)
        #pragma unroll
        for (int j = 0; j < 4; j++) acc[i][j] = 0.0f;

    for (int kt = 0; kt < K; kt += 16) {
        #pragma unroll
        for (int q0 = 0; q0 < 2; q0++) {
            int q = tid + q0 * 256;
            int r = q >> 2;
            int kb = (q & 3) * 4;
            int row = m0 + r;
            float4 v = make_float4(0.f, 0.f, 0.f, 0.f);
            if (row < M) {
                v = *(const float4*)(A + (size_t)row * K + kt + kb);
                if (FMAX) {
                    float4 v2 = *(const float4*)(A2 + (size_t)row * K + kt + kb);
                    float4 bb = *(const float4*)(ab + kt + kb);
                    v.x = fmaxf(v.x, v2.x + bb.x);
                    v.y = fmaxf(v.y, v2.y + bb.y);
                    v.z = fmaxf(v.z, v2.z + bb.z);
                    v.w = fmaxf(v.w, v2.w + bb.w);
                }
            }
            As[kb + 0][r] = v.x;
            As[kb + 1][r] = v.y;
            As[kb + 2][r] = v.z;
            As[kb + 3][r] = v.w;
        }
        {
            int r = tid >> 4;
            int n = (tid & 15) * 4;
            *(float4*)&Bs[r][n] = *(const float4*)(B + (size_t)(kt + r) * Nc + n0 + n);
        }
        __syncthreads();

        #pragma unroll
        for (int kk = 0; kk < 16; kk++) {
            float4 a0 = *(const float4*)&As[kk][ty * 8];
            float4 a1 = *(const float4*)&As[kk][ty * 8 + 4];
            float4 bv = *(const float4*)&Bs[kk][tx * 4];
            float a[8] = {a0.x, a0.y, a0.z, a0.w, a1.x, a1.y, a1.z, a1.w};
            float b[4] = {bv.x, bv.y, bv.z, bv.w};
            #pragma unroll
            for (int i = 0; i < 8; i++)
                #pragma unroll
                for (int j = 0; j < 4; j++)
                    acc[i][j] = fmaf(a[i], b[j], acc[i][j]);
        }
        __syncthreads();
    }

    float4 bv = make_float4(0.f, 0.f, 0.f, 0.f);
    if (BIAS) bv = *(const float4*)(bias + n0 + tx * 4);
    #pragma unroll
    for (int i = 0; i < 8; i++) {
        int row = m0 + ty * 8 + i;
        if (row < M) {
            float4 v = make_float4(acc[i][0] + bv.x, acc[i][1] + bv.y,
                                   acc[i][2] + bv.z, acc[i][3] + bv.w);
            *(float4*)(C + (size_t)row * Nc + n0 + tx * 4) = v;
        }
    }

    if (ALPHA) {
        // per-row dots with aS/aD over this head's 64 channels.
        const int head = n0 >> 6;
        float4 sv = *(const float4*)(aS + n0 + tx * 4);
        float4 dv = *(const float4*)(aD + n0 + tx * 4);
        #pragma unroll
        for (int i = 0; i < 8; i++) {
            float ps = acc[i][0] * sv.x + acc[i][1] * sv.y
                     + acc[i][2] * sv.z + acc[i][3] * sv.w;
            float pd = acc[i][0] * dv.x + acc[i][1] * dv.y
                     + acc[i][2] * dv.z + acc[i][3] * dv.w;
            #pragma unroll
            for (int o = 8; o; o >>= 1) {
                ps += __shfl_xor_sync(0xffffffffu, ps, o);
                pd += __shfl_xor_sync(0xffffffffu, pd, o);
            }
            int row = m0 + ty * 8 + i;
            if (tx == 0 && row < M) {
                g_asrc[row * 4 + head] = ps;
                g_adst[row * 4 + head] = pd;
            }
        }
    }
}

// ---------------- fused edge-softmax + CSR gather ----------------
// 64 threads per node: thread = (head = t>>4, quad q = t&15 -> 4 channels).
// w = exp(leaky_relu(asrc[s]+adst[d])) computed in-loop (lane-redundant = free).
// ACT=true: apply bias + BatchNorm(eval) + ELU (layer 0 epilogue).
template <bool ACT>
__global__ __launch_bounds__(256) void gather_k(
    const float* __restrict__ h, float* __restrict__ out,
    const float* __restrict__ b0,
    const float* __restrict__ gamma,
    const float* __restrict__ beta)
{
    int node = blockIdx.x * 4 + (threadIdx.x >> 6);
    if (node >= NN) return;
    int t = threadIdx.x & 63;
    int head = t >> 4;
    int q = t & 15;
    int p = g_off[node];
    const int end = g_off[node + 1];

    const float ad = g_adst[node * 4 + head];
    float4 acc = make_float4(0.f, 0.f, 0.f, 0.f);
    float wsum = 0.f;

    const int coff = head * 64 + q * 4;
    for (; p < end; p++) {
        int s = g_adj[p];
        float e = g_asrc[s * 4 + head] + ad;
        e = e > 0.f ? e : 0.2f * e;
        float w = __expf(e);
        float4 hv = *(const float4*)(h + (size_t)s * HC + coff);
        acc.x = fmaf(w, hv.x, acc.x);
        acc.y = fmaf(w, hv.y, acc.y);
        acc.z = fmaf(w, hv.z, acc.z);
        acc.w = fmaf(w, hv.w, acc.w);
        wsum += w;
    }
    float inv = 1.0f / (wsum + 1e-16f);
    acc.x *= inv; acc.y *= inv; acc.z *= inv; acc.w *= inv;

    float* op = out + (size_t)node * HC + coff;
    if (ACT) {
        const float r = rsqrtf(1.0f + 1e-5f);
        float4 bb = *(const float4*)(b0 + coff);
        float4 gg = *(const float4*)(gamma + coff);
        float4 be = *(const float4*)(beta + coff);
        float v0 = (acc.x + bb.x) * (gg.x * r) + be.x;
        float v1 = (acc.y + bb.y) * (gg.y * r) + be.y;
        float v2 = (acc.z + bb.z) * (gg.z * r) + be.z;
        float v3 = (acc.w + bb.w) * (gg.w * r) + be.w;
        float4 o;
        o.x = v0 > 0.f ? v0 : expm1f(v0);
        o.y = v1 > 0.f ? v1 : expm1f(v1);
        o.z = v2 > 0.f ? v2 : expm1f(v2);
        o.w = v3 > 0.f ? v3 : expm1f(v3);
        *(float4*)op = o;
    } else {
        *(float4*)op = acc;
    }
}

// ---------------- launch ----------------
extern "C" void kernel_launch(void* const* d_in, const int* in_sizes, int n_in,
                              void* d_out, int out_size)
{
    const float* x      = (const float*)d_in[0];
    const void*  ei     = d_in[1];
    const float* W0     = (const float*)d_in[2];
    const float* as0    = (const float*)d_in[3];
    const float* ad0    = (const float*)d_in[4];
    const float* b0     = (const float*)d_in[5];
    const float* gamma0 = (const float*)d_in[6];
    const float* beta0  = (const float*)d_in[7];
    const float* W1     = (const float*)d_in[8];
    const float* as1    = (const float*)d_in[9];
    const float* ad1    = (const float*)d_in[10];
    const float* b1     = (const float*)d_in[11];
    const float* Wf     = (const float*)d_in[12];
    const float* bf     = (const float*)d_in[13];
    float* out = (float*)d_out;

    float *h, *x1, *acc;
    int* deg;
    cudaGetSymbolAddress((void**)&h,   g_h);
    cudaGetSymbolAddress((void**)&x1,  g_x1);
    cudaGetSymbolAddress((void**)&acc, g_acc);
    cudaGetSymbolAddress((void**)&deg, g_deg);

    const int mb = (NN + 127) / 128;
    const int eb = (NET + 255) / 256;
    const int gb = (NN + 3) / 4;

    detect_k<<<1, 32>>>((const int*)ei);

    // ---- CSR build (shared by both layers) ----
    zeroi_k<<<(NN + 255) / 256, 256>>>(deg, NN);
    hist_k<<<eb, 256>>>(ei);
    scan1_k<<<NB_SCAN, 256>>>();
    scan2_k<<<1, 256>>>();
    scan3_k<<<NB_SCAN, 256>>>();
    fill_k<<<eb, 256>>>(ei);

    // ---- layer 0 ----
    gemm_k<true, false, false><<<dim3(HC / 64, mb), 256>>>(
        x, nullptr, nullptr, W0, nullptr, as0, ad0, h, NN, 128, HC);
    gather_k<true><<<gb, 256>>>(h, x1, b0, gamma0, beta0);

    // ---- layer 1 ----
    gemm_k<true, false, false><<<dim3(HC / 64, mb), 256>>>(
        x1, nullptr, nullptr, W1, nullptr, as1, ad1, h, NN, HC, HC);
    gather_k<false><<<gb, 256>>>(h, acc, nullptr, nullptr, nullptr);

    // ---- JK-max + final projection: out = max(x1, acc + b1) @ Wf + bf ----
    gemm_k<false, true, true><<<dim3(1, mb), 256>>>(
        x1, acc, b1, Wf, bf, nullptr, nullptr, out, NN, HC, 64);
}

// round 4
// speedup vs baseline: 2.5356x; 1.0773x over previous
#include <cuda_runtime.h>
#include <cuda_fp16.h>
#include <math.h>

#define NN 50000
#define NE 800000
#define NET (NE + NN)       // edges + self loops = 850000
#define HC 256              // H*C
#define NH 4
#define CC 64
#define NB_SCAN 196         // ceil(NN/256)

// ---------------- scratch (static device globals; no allocs) ----------------
__device__ __align__(16) __half g_h[NN * HC];     // transformed features (fp16, per layer)
__device__ __align__(16) float g_x1[NN * HC];     // layer-0 activated output
__device__ __align__(16) float g_acc[NN * HC];    // layer-1 aggregation output
__device__ __align__(16) float g_asrc[NN * NH];
__device__ __align__(16) float g_adst[NN * NH];
__device__ int g_deg[NN];
__device__ int g_off[NN + 1];
__device__ int g_cur[NN];
__device__ int g_part[NB_SCAN];
__device__ int g_adj[NET];                        // src ids grouped by dst
__device__ int g_is64;

// ---------------- utility ----------------
__global__ void zeroi_k(int* p, int n) {
    int i = blockIdx.x * blockDim.x + threadIdx.x;
    if (i < n) p[i] = 0;
}

// Detect whether edge_index is int64 (high 32-bit words of first 64 values are 0)
__global__ void detect_k(const int* ei32) {
    if (threadIdx.x == 0 && blockIdx.x == 0) {
        int ok = 1;
        #pragma unroll
        for (int k = 0; k < 64; k++)
            if (ei32[2 * k + 1] != 0) ok = 0;
        g_is64 = ok;
    }
}

__device__ __forceinline__ void edge_sd(const void* ei, int e, int& s, int& d) {
    if (e >= NE) { s = d = e - NE; return; }
    if (g_is64) {
        const long long* p = (const long long*)ei;
        s = (int)p[e];
        d = (int)p[NE + e];
    } else {
        const int* p = (const int*)ei;
        s = p[e];
        d = p[NE + e];
    }
}

// ---------------- CSR build ----------------
__global__ void hist_k(const void* __restrict__ ei) {
    int e = blockIdx.x * blockDim.x + threadIdx.x;
    if (e >= NET) return;
    int s, d;
    edge_sd(ei, e, s, d);
    atomicAdd(&g_deg[d], 1);
}

__global__ void scan1_k() {   // per-block sums of deg
    __shared__ int sh[256];
    int i = blockIdx.x * 256 + threadIdx.x;
    int v = (i < NN) ? g_deg[i] : 0;
    sh[threadIdx.x] = v; __syncthreads();
    for (int o = 128; o; o >>= 1) {
        if (threadIdx.x < o) sh[threadIdx.x] += sh[threadIdx.x + o];
        __syncthreads();
    }
    if (threadIdx.x == 0) g_part[blockIdx.x] = sh[0];
}

__global__ void scan2_k() {   // exclusive scan of NB_SCAN partials (1 block)
    __shared__ int sh[256];
    int t = threadIdx.x;
    int v = (t < NB_SCAN) ? g_part[t] : 0;
    sh[t] = v; __syncthreads();
    for (int o = 1; o < 256; o <<= 1) {
        int x = (t >= o) ? sh[t - o] : 0;
        __syncthreads();
        sh[t] += x;
        __syncthreads();
    }
    if (t < NB_SCAN) g_part[t] = sh[t] - v;   // exclusive
}

__global__ void scan3_k() {   // per-block exclusive scan + offset -> off, cur
    __shared__ int sh[256];
    int t = threadIdx.x;
    int i = blockIdx.x * 256 + t;
    int v = (i < NN) ? g_deg[i] : 0;
    sh[t] = v; __syncthreads();
    for (int o = 1; o < 256; o <<= 1) {
        int x = (t >= o) ? sh[t - o] : 0;
        __syncthreads();
        sh[t] += x;
        __syncthreads();
    }
    if (i < NN) {
        int off = g_part[blockIdx.x] + sh[t] - v;
        g_off[i] = off;
        g_cur[i] = off;
        if (i == NN - 1) g_off[NN] = off + v;
    }
}

__global__ void fill_k(const void* __restrict__ ei) {
    int e = blockIdx.x * blockDim.x + threadIdx.x;
    if (e >= NET) return;
    int s, d;
    edge_sd(ei, e, s, d);
    int p = atomicAdd(&g_cur[d], 1);
    g_adj[p] = s;
}

// ---------------- GEMM: C[M,Nc] = A[M,K] @ B[K,Nc] (+bias) ----------------
// ALPHA: also compute per-row attention dots with aS/aD (one head per block col).
// FMAX: A-element = max(A[m,k], A2[m,k] + ab[k])  (fused JK-max + bias)
// OUTHALF: store C as fp16 (message features consumed only by gather).
template <bool ALPHA, bool FMAX, bool BIAS, bool OUTHALF>
__global__ __launch_bounds__(256) void gemm_k(
    const float* __restrict__ A, const float* __restrict__ A2,
    const float* __restrict__ ab, const float* __restrict__ B,
    const float* __restrict__ bias,
    const float* __restrict__ aS, const float* __restrict__ aD,
    void* __restrict__ Cv,
    int M, int K, int Nc)
{
    __shared__ float As[16][132];
    __shared__ float Bs[16][64];
    const int tid = threadIdx.x;
    const int m0 = blockIdx.y * 128;
    const int n0 = blockIdx.x * 64;
    const int ty = tid >> 4;
    const int tx = tid & 15;

    float acc[8][4];
    #pragma unroll
    for (int i = 0; i < 8; i++)
        #pragma unroll
        for (int j = 0; j < 4; j++) acc[i][j] = 0.0f;

    for (int kt = 0; kt < K; kt += 16) {
        #pragma unroll
        for (int q0 = 0; q0 < 2; q0++) {
            int q = tid + q0 * 256;
            int r = q >> 2;
            int kb = (q & 3) * 4;
            int row = m0 + r;
            float4 v = make_float4(0.f, 0.f, 0.f, 0.f);
            if (row < M) {
                v = *(const float4*)(A + (size_t)row * K + kt + kb);
                if (FMAX) {
                    float4 v2 = *(const float4*)(A2 + (size_t)row * K + kt + kb);
                    float4 bb = *(const float4*)(ab + kt + kb);
                    v.x = fmaxf(v.x, v2.x + bb.x);
                    v.y = fmaxf(v.y, v2.y + bb.y);
                    v.z = fmaxf(v.z, v2.z + bb.z);
                    v.w = fmaxf(v.w, v2.w + bb.w);
                }
            }
            As[kb + 0][r] = v.x;
            As[kb + 1][r] = v.y;
            As[kb + 2][r] = v.z;
            As[kb + 3][r] = v.w;
        }
        {
            int r = tid >> 4;
            int n = (tid & 15) * 4;
            *(float4*)&Bs[r][n] = *(const float4*)(B + (size_t)(kt + r) * Nc + n0 + n);
        }
        __syncthreads();

        #pragma unroll
        for (int kk = 0; kk < 16; kk++) {
            float4 a0 = *(const float4*)&As[kk][ty * 8];
            float4 a1 = *(const float4*)&As[kk][ty * 8 + 4];
            float4 bv = *(const float4*)&Bs[kk][tx * 4];
            float a[8] = {a0.x, a0.y, a0.z, a0.w, a1.x, a1.y, a1.z, a1.w};
            float b[4] = {bv.x, bv.y, bv.z, bv.w};
            #pragma unroll
            for (int i = 0; i < 8; i++)
                #pragma unroll
                for (int j = 0; j < 4; j++)
                    acc[i][j] = fmaf(a[i], b[j], acc[i][j]);
        }
        __syncthreads();
    }

    float4 bv = make_float4(0.f, 0.f, 0.f, 0.f);
    if (BIAS) bv = *(const float4*)(bias + n0 + tx * 4);
    #pragma unroll
    for (int i = 0; i < 8; i++) {
        int row = m0 + ty * 8 + i;
        if (row < M) {
            float4 v = make_float4(acc[i][0] + bv.x, acc[i][1] + bv.y,
                                   acc[i][2] + bv.z, acc[i][3] + bv.w);
            if (OUTHALF) {
                __half2 p0 = __floats2half2_rn(v.x, v.y);
                __half2 p1 = __floats2half2_rn(v.z, v.w);
                __half2* cp = (__half2*)((__half*)Cv + (size_t)row * Nc + n0 + tx * 4);
                cp[0] = p0;
                cp[1] = p1;
            } else {
                *(float4*)((float*)Cv + (size_t)row * Nc + n0 + tx * 4) = v;
            }
        }
    }

    if (ALPHA) {
        // per-row dots with aS/aD over this head's 64 channels (fp32 accs).
        const int head = n0 >> 6;
        float4 sv = *(const float4*)(aS + n0 + tx * 4);
        float4 dv = *(const float4*)(aD + n0 + tx * 4);
        #pragma unroll
        for (int i = 0; i < 8; i++) {
            float ps = acc[i][0] * sv.x + acc[i][1] * sv.y
                     + acc[i][2] * sv.z + acc[i][3] * sv.w;
            float pd = acc[i][0] * dv.x + acc[i][1] * dv.y
                     + acc[i][2] * dv.z + acc[i][3] * dv.w;
            #pragma unroll
            for (int o = 8; o; o >>= 1) {
                ps += __shfl_xor_sync(0xffffffffu, ps, o);
                pd += __shfl_xor_sync(0xffffffffu, pd, o);
            }
            int row = m0 + ty * 8 + i;
            if (tx == 0 && row < M) {
                g_asrc[row * 4 + head] = ps;
                g_adst[row * 4 + head] = pd;
            }
        }
    }
}

// ---------------- fused edge-softmax + CSR gather (fp16 features) ----------------
// 32 threads per node: thread = (head = t>>3, octet = t&7 -> 8 channels).
// 8 nodes per 256-thread block. fp32 accumulation, fp32 output.
// ACT=true: apply bias + BatchNorm(eval) + ELU (layer 0 epilogue).
template <bool ACT>
__global__ __launch_bounds__(256) void gather_k(
    const __half* __restrict__ h, float* __restrict__ out,
    const float* __restrict__ b0,
    const float* __restrict__ gamma,
    const float* __restrict__ beta)
{
    int node = blockIdx.x * 8 + (threadIdx.x >> 5);
    if (node >= NN) return;
    int t = threadIdx.x & 31;
    int head = t >> 3;
    int oct = t & 7;
    int p = g_off[node];
    const int end = g_off[node + 1];

    const float ad = g_adst[node * 4 + head];
    float a[8];
    #pragma unroll
    for (int i = 0; i < 8; i++) a[i] = 0.f;
    float wsum = 0.f;

    const int coff = head * 64 + oct * 8;
    for (; p < end; p++) {
        int s = g_adj[p];
        float e = g_asrc[s * 4 + head] + ad;
        e = e > 0.f ? e : 0.2f * e;
        float w = __expf(e);
        uint4 raw = *(const uint4*)(h + (size_t)s * HC + coff);
        float2 f0 = __half22float2(*(__half2*)&raw.x);
        float2 f1 = __half22float2(*(__half2*)&raw.y);
        float2 f2 = __half22float2(*(__half2*)&raw.z);
        float2 f3 = __half22float2(*(__half2*)&raw.w);
        a[0] = fmaf(w, f0.x, a[0]);
        a[1] = fmaf(w, f0.y, a[1]);
        a[2] = fmaf(w, f1.x, a[2]);
        a[3] = fmaf(w, f1.y, a[3]);
        a[4] = fmaf(w, f2.x, a[4]);
        a[5] = fmaf(w, f2.y, a[5]);
        a[6] = fmaf(w, f3.x, a[6]);
        a[7] = fmaf(w, f3.y, a[7]);
        wsum += w;
    }
    float inv = 1.0f / (wsum + 1e-16f);
    #pragma unroll
    for (int i = 0; i < 8; i++) a[i] *= inv;

    float* op = out + (size_t)node * HC + coff;
    if (ACT) {
        const float r = rsqrtf(1.0f + 1e-5f);
        #pragma unroll
        for (int u = 0; u < 2; u++) {
            float4 bb = *(const float4*)(b0 + coff + u * 4);
            float4 gg = *(const float4*)(gamma + coff + u * 4);
            float4 be = *(const float4*)(beta + coff + u * 4);
            float v0 = (a[u * 4 + 0] + bb.x) * (gg.x * r) + be.x;
            float v1 = (a[u * 4 + 1] + bb.y) * (gg.y * r) + be.y;
            float v2 = (a[u * 4 + 2] + bb.z) * (gg.z * r) + be.z;
            float v3 = (a[u * 4 + 3] + bb.w) * (gg.w * r) + be.w;
            float4 o;
            o.x = v0 > 0.f ? v0 : expm1f(v0);
            o.y = v1 > 0.f ? v1 : expm1f(v1);
            o.z = v2 > 0.f ? v2 : expm1f(v2);
            o.w = v3 > 0.f ? v3 : expm1f(v3);
            *(float4*)(op + u * 4) = o;
        }
    } else {
        *(float4*)op = make_float4(a[0], a[1], a[2], a[3]);
        *(float4*)(op + 4) = make_float4(a[4], a[5], a[6], a[7]);
    }
}

// ---------------- launch ----------------
extern "C" void kernel_launch(void* const* d_in, const int* in_sizes, int n_in,
                              void* d_out, int out_size)
{
    const float* x      = (const float*)d_in[0];
    const void*  ei     = d_in[1];
    const float* W0     = (const float*)d_in[2];
    const float* as0    = (const float*)d_in[3];
    const float* ad0    = (const float*)d_in[4];
    const float* b0     = (const float*)d_in[5];
    const float* gamma0 = (const float*)d_in[6];
    const float* beta0  = (const float*)d_in[7];
    const float* W1     = (const float*)d_in[8];
    const float* as1    = (const float*)d_in[9];
    const float* ad1    = (const float*)d_in[10];
    const float* b1     = (const float*)d_in[11];
    const float* Wf     = (const float*)d_in[12];
    const float* bf     = (const float*)d_in[13];
    float* out = (float*)d_out;

    __half* h;
    float *x1, *acc;
    int* deg;
    cudaGetSymbolAddress((void**)&h,   g_h);
    cudaGetSymbolAddress((void**)&x1,  g_x1);
    cudaGetSymbolAddress((void**)&acc, g_acc);
    cudaGetSymbolAddress((void**)&deg, g_deg);

    const int mb = (NN + 127) / 128;
    const int eb = (NET + 255) / 256;
    const int gb = (NN + 7) / 8;

    detect_k<<<1, 32>>>((const int*)ei);

    // ---- CSR build (shared by both layers) ----
    zeroi_k<<<(NN + 255) / 256, 256>>>(deg, NN);
    hist_k<<<eb, 256>>>(ei);
    scan1_k<<<NB_SCAN, 256>>>();
    scan2_k<<<1, 256>>>();
    scan3_k<<<NB_SCAN, 256>>>();
    fill_k<<<eb, 256>>>(ei);

    // ---- layer 0 ----
    gemm_k<true, false, false, true><<<dim3(HC / 64, mb), 256>>>(
        x, nullptr, nullptr, W0, nullptr, as0, ad0, h, NN, 128, HC);
    gather_k<true><<<gb, 256>>>(h, x1, b0, gamma0, beta0);

    // ---- layer 1 ----
    gemm_k<true, false, false, true><<<dim3(HC / 64, mb), 256>>>(
        x1, nullptr, nullptr, W1, nullptr, as1, ad1, h, NN, HC, HC);
    gather_k<false><<<gb, 256>>>(h, acc, nullptr, nullptr, nullptr);

    // ---- JK-max + final projection: out = max(x1, acc + b1) @ Wf + bf ----
    gemm_k<false, true, true, false><<<dim3(1, mb), 256>>>(
        x1, acc, b1, Wf, bf, nullptr, nullptr, out, NN, HC, 64);
}

// round 5
// speedup vs baseline: 2.5828x; 1.0186x over previous
#include <cuda_runtime.h>
#include <cuda_fp16.h>
#include <math.h>

#define NN 50000
#define NE 800000
#define NET (NE + NN)       // edges + self loops = 850000
#define HC 256              // H*C
#define NH 4
#define CC 64
#define NB_SCAN 196         // ceil(NN/256)

// ---------------- scratch (static device globals; no allocs) ----------------
__device__ __align__(16) __half g_h[NN * HC];     // transformed features (fp16, per layer)
__device__ __align__(16) float g_x1[NN * HC];     // layer-0 activated output
__device__ __align__(16) float g_acc[NN * HC];    // layer-1 aggregation output
__device__ __align__(16) float g_asrc[NN * NH];
__device__ __align__(16) float g_adst[NN * NH];
__device__ int g_deg[NN];
__device__ int g_off[NN + 1];
__device__ int g_cur[NN];
__device__ int g_part[NB_SCAN];
__device__ int g_adj[NET];                        // src ids grouped by dst
__device__ int g_is64;

// ---------------- utility ----------------
__global__ void zeroi_k(int* p, int n) {
    int i = blockIdx.x * blockDim.x + threadIdx.x;
    if (i < n) p[i] = 0;
}

// Detect whether edge_index is int64 (high 32-bit words of first 64 values are 0)
__global__ void detect_k(const int* ei32) {
    if (threadIdx.x == 0 && blockIdx.x == 0) {
        int ok = 1;
        #pragma unroll
        for (int k = 0; k < 64; k++)
            if (ei32[2 * k + 1] != 0) ok = 0;
        g_is64 = ok;
    }
}

__device__ __forceinline__ void edge_sd(const void* ei, int e, int& s, int& d) {
    if (e >= NE) { s = d = e - NE; return; }
    if (g_is64) {
        const long long* p = (const long long*)ei;
        s = (int)p[e];
        d = (int)p[NE + e];
    } else {
        const int* p = (const int*)ei;
        s = p[e];
        d = p[NE + e];
    }
}

// ---------------- CSR build ----------------
__global__ void hist_k(const void* __restrict__ ei) {
    int e = blockIdx.x * blockDim.x + threadIdx.x;
    if (e >= NET) return;
    int s, d;
    edge_sd(ei, e, s, d);
    atomicAdd(&g_deg[d], 1);
}

__global__ void scan1_k() {   // per-block sums of deg
    __shared__ int sh[256];
    int i = blockIdx.x * 256 + threadIdx.x;
    int v = (i < NN) ? g_deg[i] : 0;
    sh[threadIdx.x] = v; __syncthreads();
    for (int o = 128; o; o >>= 1) {
        if (threadIdx.x < o) sh[threadIdx.x] += sh[threadIdx.x + o];
        __syncthreads();
    }
    if (threadIdx.x == 0) g_part[blockIdx.x] = sh[0];
}

__global__ void scan2_k() {   // exclusive scan of NB_SCAN partials (1 block)
    __shared__ int sh[256];
    int t = threadIdx.x;
    int v = (t < NB_SCAN) ? g_part[t] : 0;
    sh[t] = v; __syncthreads();
    for (int o = 1; o < 256; o <<= 1) {
        int x = (t >= o) ? sh[t - o] : 0;
        __syncthreads();
        sh[t] += x;
        __syncthreads();
    }
    if (t < NB_SCAN) g_part[t] = sh[t] - v;   // exclusive
}

__global__ void scan3_k() {   // per-block exclusive scan + offset -> off, cur
    __shared__ int sh[256];
    int t = threadIdx.x;
    int i = blockIdx.x * 256 + t;
    int v = (i < NN) ? g_deg[i] : 0;
    sh[t] = v; __syncthreads();
    for (int o = 1; o < 256; o <<= 1) {
        int x = (t >= o) ? sh[t - o] : 0;
        __syncthreads();
        sh[t] += x;
        __syncthreads();
    }
    if (i < NN) {
        int off = g_part[blockIdx.x] + sh[t] - v;
        g_off[i] = off;
        g_cur[i] = off;
        if (i == NN - 1) g_off[NN] = off + v;
    }
}

__global__ void fill_k(const void* __restrict__ ei) {
    int e = blockIdx.x * blockDim.x + threadIdx.x;
    if (e >= NET) return;
    int s, d;
    edge_sd(ei, e, s, d);
    int p = atomicAdd(&g_cur[d], 1);
    g_adj[p] = s;
}

// ---------------- GEMM: C[M,Nc] = A[M,K] @ B[K,Nc] (+bias) ----------------
// ALPHA: also compute per-row attention dots with aS/aD (one head per block col).
// FMAX: A-element = max(A[m,k], A2[m,k] + ab[k])  (fused JK-max + bias)
// OUTHALF: store C as fp16 (message features consumed only by gather).
template <bool ALPHA, bool FMAX, bool BIAS, bool OUTHALF>
__global__ __launch_bounds__(256) void gemm_k(
    const float* __restrict__ A, const float* __restrict__ A2,
    const float* __restrict__ ab, const float* __restrict__ B,
    const float* __restrict__ bias,
    const float* __restrict__ aS, const float* __restrict__ aD,
    void* __restrict__ Cv,
    int M, int K, int Nc)
{
    __shared__ float As[16][132];
    __shared__ float Bs[16][64];
    const int tid = threadIdx.x;
    const int m0 = blockIdx.y * 128;
    const int n0 = blockIdx.x * 64;
    const int ty = tid >> 4;
    const int tx = tid & 15;

    float acc[8][4];
    #pragma unroll
    for (int i = 0; i < 8; i++)
        #pragma unroll
        for (int j = 0; j < 4; j++) acc[i][j] = 0.0f;

    for (int kt = 0; kt < K; kt += 16) {
        #pragma unroll
        for (int q0 = 0; q0 < 2; q0++) {
            int q = tid + q0 * 256;
            int r = q >> 2;
            int kb = (q & 3) * 4;
            int row = m0 + r;
            float4 v = make_float4(0.f, 0.f, 0.f, 0.f);
            if (row < M) {
                v = *(const float4*)(A + (size_t)row * K + kt + kb);
                if (FMAX) {
                    float4 v2 = *(const float4*)(A2 + (size_t)row * K + kt + kb);
                    float4 bb = *(const float4*)(ab + kt + kb);
                    v.x = fmaxf(v.x, v2.x + bb.x);
                    v.y = fmaxf(v.y, v2.y + bb.y);
                    v.z = fmaxf(v.z, v2.z + bb.z);
                    v.w = fmaxf(v.w, v2.w + bb.w);
                }
            }
            As[kb + 0][r] = v.x;
            As[kb + 1][r] = v.y;
            As[kb + 2][r] = v.z;
            As[kb + 3][r] = v.w;
        }
        {
            int r = tid >> 4;
            int n = (tid & 15) * 4;
            *(float4*)&Bs[r][n] = *(const float4*)(B + (size_t)(kt + r) * Nc + n0 + n);
        }
        __syncthreads();

        #pragma unroll
        for (int kk = 0; kk < 16; kk++) {
            float4 a0 = *(const float4*)&As[kk][ty * 8];
            float4 a1 = *(const float4*)&As[kk][ty * 8 + 4];
            float4 bv = *(const float4*)&Bs[kk][tx * 4];
            float a[8] = {a0.x, a0.y, a0.z, a0.w, a1.x, a1.y, a1.z, a1.w};
            float b[4] = {bv.x, bv.y, bv.z, bv.w};
            #pragma unroll
            for (int i = 0; i < 8; i++)
                #pragma unroll
                for (int j = 0; j < 4; j++)
                    acc[i][j] = fmaf(a[i], b[j], acc[i][j]);
        }
        __syncthreads();
    }

    float4 bv = make_float4(0.f, 0.f, 0.f, 0.f);
    if (BIAS) bv = *(const float4*)(bias + n0 + tx * 4);
    #pragma unroll
    for (int i = 0; i < 8; i++) {
        int row = m0 + ty * 8 + i;
        if (row < M) {
            float4 v = make_float4(acc[i][0] + bv.x, acc[i][1] + bv.y,
                                   acc[i][2] + bv.z, acc[i][3] + bv.w);
            if (OUTHALF) {
                __half2 p0 = __floats2half2_rn(v.x, v.y);
                __half2 p1 = __floats2half2_rn(v.z, v.w);
                __half2* cp = (__half2*)((__half*)Cv + (size_t)row * Nc + n0 + tx * 4);
                cp[0] = p0;
                cp[1] = p1;
            } else {
                *(float4*)((float*)Cv + (size_t)row * Nc + n0 + tx * 4) = v;
            }
        }
    }

    if (ALPHA) {
        // per-row dots with aS/aD over this head's 64 channels (fp32 accs).
        const int head = n0 >> 6;
        float4 sv = *(const float4*)(aS + n0 + tx * 4);
        float4 dv = *(const float4*)(aD + n0 + tx * 4);
        #pragma unroll
        for (int i = 0; i < 8; i++) {
            float ps = acc[i][0] * sv.x + acc[i][1] * sv.y
                     + acc[i][2] * sv.z + acc[i][3] * sv.w;
            float pd = acc[i][0] * dv.x + acc[i][1] * dv.y
                     + acc[i][2] * dv.z + acc[i][3] * dv.w;
            #pragma unroll
            for (int o = 8; o; o >>= 1) {
                ps += __shfl_xor_sync(0xffffffffu, ps, o);
                pd += __shfl_xor_sync(0xffffffffu, pd, o);
            }
            int row = m0 + ty * 8 + i;
            if (tx == 0 && row < M) {
                g_asrc[row * 4 + head] = ps;
                g_adst[row * 4 + head] = pd;
            }
        }
    }
}

// ---------------- fused edge-softmax + CSR gather (fp16 features) ----------------
// 32 threads per node: thread = (head = t>>3, octet = t&7 -> 8 channels).
// 8 nodes per 256-thread block. 4x unrolled for MLP. fp32 accumulation.
// ACT=true: apply bias + BatchNorm(eval) + ELU (layer 0 epilogue).
template <bool ACT>
__global__ __launch_bounds__(256) void gather_k(
    const __half* __restrict__ h, float* __restrict__ out,
    const float* __restrict__ b0,
    const float* __restrict__ gamma,
    const float* __restrict__ beta)
{
    int node = blockIdx.x * 8 + (threadIdx.x >> 5);
    if (node >= NN) return;
    int t = threadIdx.x & 31;
    int head = t >> 3;
    int oct = t & 7;
    int p = g_off[node];
    const int end = g_off[node + 1];

    const float ad = g_adst[node * 4 + head];
    float a[8];
    #pragma unroll
    for (int i = 0; i < 8; i++) a[i] = 0.f;
    float wsum = 0.f;

    const int coff = head * 64 + oct * 8;

    // 4x unrolled main loop: batch index/alpha/feature loads for MLP.
    for (; p + 4 <= end; p += 4) {
        int s0 = g_adj[p + 0];
        int s1 = g_adj[p + 1];
        int s2 = g_adj[p + 2];
        int s3 = g_adj[p + 3];
        float e0 = g_asrc[s0 * 4 + head] + ad;
        float e1 = g_asrc[s1 * 4 + head] + ad;
        float e2 = g_asrc[s2 * 4 + head] + ad;
        float e3 = g_asrc[s3 * 4 + head] + ad;
        uint4 r0 = *(const uint4*)(h + (size_t)s0 * HC + coff);
        uint4 r1 = *(const uint4*)(h + (size_t)s1 * HC + coff);
        uint4 r2 = *(const uint4*)(h + (size_t)s2 * HC + coff);
        uint4 r3 = *(const uint4*)(h + (size_t)s3 * HC + coff);
        e0 = e0 > 0.f ? e0 : 0.2f * e0;
        e1 = e1 > 0.f ? e1 : 0.2f * e1;
        e2 = e2 > 0.f ? e2 : 0.2f * e2;
        e3 = e3 > 0.f ? e3 : 0.2f * e3;
        float w0 = __expf(e0), w1 = __expf(e1), w2 = __expf(e2), w3 = __expf(e3);
        wsum += (w0 + w1) + (w2 + w3);
        const uint4* rr[4] = {&r0, &r1, &r2, &r3};
        float ww[4] = {w0, w1, w2, w3};
        #pragma unroll
        for (int u = 0; u < 4; u++) {
            float2 f0 = __half22float2(*(const __half2*)&rr[u]->x);
            float2 f1 = __half22float2(*(const __half2*)&rr[u]->y);
            float2 f2 = __half22float2(*(const __half2*)&rr[u]->z);
            float2 f3 = __half22float2(*(const __half2*)&rr[u]->w);
            float w = ww[u];
            a[0] = fmaf(w, f0.x, a[0]);
            a[1] = fmaf(w, f0.y, a[1]);
            a[2] = fmaf(w, f1.x, a[2]);
            a[3] = fmaf(w, f1.y, a[3]);
            a[4] = fmaf(w, f2.x, a[4]);
            a[5] = fmaf(w, f2.y, a[5]);
            a[6] = fmaf(w, f3.x, a[6]);
            a[7] = fmaf(w, f3.y, a[7]);
        }
    }
    for (; p < end; p++) {
        int s = g_adj[p];
        float e = g_asrc[s * 4 + head] + ad;
        e = e > 0.f ? e : 0.2f * e;
        float w = __expf(e);
        uint4 raw = *(const uint4*)(h + (size_t)s * HC + coff);
        float2 f0 = __half22float2(*(__half2*)&raw.x);
        float2 f1 = __half22float2(*(__half2*)&raw.y);
        float2 f2 = __half22float2(*(__half2*)&raw.z);
        float2 f3 = __half22float2(*(__half2*)&raw.w);
        a[0] = fmaf(w, f0.x, a[0]);
        a[1] = fmaf(w, f0.y, a[1]);
        a[2] = fmaf(w, f1.x, a[2]);
        a[3] = fmaf(w, f1.y, a[3]);
        a[4] = fmaf(w, f2.x, a[4]);
        a[5] = fmaf(w, f2.y, a[5]);
        a[6] = fmaf(w, f3.x, a[6]);
        a[7] = fmaf(w, f3.y, a[7]);
        wsum += w;
    }

    float inv = 1.0f / (wsum + 1e-16f);
    #pragma unroll
    for (int i = 0; i < 8; i++) a[i] *= inv;

    float* op = out + (size_t)node * HC + coff;
    if (ACT) {
        const float r = rsqrtf(1.0f + 1e-5f);
        #pragma unroll
        for (int u = 0; u < 2; u++) {
            float4 bb = *(const float4*)(b0 + coff + u * 4);
            float4 gg = *(const float4*)(gamma + coff + u * 4);
            float4 be = *(const float4*)(beta + coff + u * 4);
            float v0 = (a[u * 4 + 0] + bb.x) * (gg.x * r) + be.x;
            float v1 = (a[u * 4 + 1] + bb.y) * (gg.y * r) + be.y;
            float v2 = (a[u * 4 + 2] + bb.z) * (gg.z * r) + be.z;
            float v3 = (a[u * 4 + 3] + bb.w) * (gg.w * r) + be.w;
            float4 o;
            o.x = v0 > 0.f ? v0 : expm1f(v0);
            o.y = v1 > 0.f ? v1 : expm1f(v1);
            o.z = v2 > 0.f ? v2 : expm1f(v2);
            o.w = v3 > 0.f ? v3 : expm1f(v3);
            *(float4*)(op + u * 4) = o;
        }
    } else {
        *(float4*)op = make_float4(a[0], a[1], a[2], a[3]);
        *(float4*)(op + 4) = make_float4(a[4], a[5], a[6], a[7]);
    }
}

// ---------------- launch ----------------
extern "C" void kernel_launch(void* const* d_in, const int* in_sizes, int n_in,
                              void* d_out, int out_size)
{
    const float* x      = (const float*)d_in[0];
    const void*  ei     = d_in[1];
    const float* W0     = (const float*)d_in[2];
    const float* as0    = (const float*)d_in[3];
    const float* ad0    = (const float*)d_in[4];
    const float* b0     = (const float*)d_in[5];
    const float* gamma0 = (const float*)d_in[6];
    const float* beta0  = (const float*)d_in[7];
    const float* W1     = (const float*)d_in[8];
    const float* as1    = (const float*)d_in[9];
    const float* ad1    = (const float*)d_in[10];
    const float* b1     = (const float*)d_in[11];
    const float* Wf     = (const float*)d_in[12];
    const float* bf     = (const float*)d_in[13];
    float* out = (float*)d_out;

    __half* h;
    float *x1, *acc;
    int* deg;
    cudaGetSymbolAddress((void**)&h,   g_h);
    cudaGetSymbolAddress((void**)&x1,  g_x1);
    cudaGetSymbolAddress((void**)&acc, g_acc);
    cudaGetSymbolAddress((void**)&deg, g_deg);

    // one-time stream/event creation (host-side resources, not device memory)
    static cudaStream_t s2 = nullptr;
    static cudaEvent_t evFork = nullptr, evJoin = nullptr;
    if (s2 == nullptr) {
        cudaStreamCreateWithFlags(&s2, cudaStreamNonBlocking);
        cudaEventCreateWithFlags(&evFork, cudaEventDisableTiming);
        cudaEventCreateWithFlags(&evJoin, cudaEventDisableTiming);
    }

    const int mb = (NN + 127) / 128;
    const int eb = (NET + 255) / 256;
    const int gb = (NN + 7) / 8;

    // ---- fork: CSR build on s2, concurrent with layer-0 GEMM on default ----
    cudaEventRecord(evFork, 0);
    cudaStreamWaitEvent(s2, evFork, 0);

    detect_k<<<1, 32, 0, s2>>>((const int*)ei);
    zeroi_k<<<(NN + 255) / 256, 256, 0, s2>>>(deg, NN);
    hist_k<<<eb, 256, 0, s2>>>(ei);
    scan1_k<<<NB_SCAN, 256, 0, s2>>>();
    scan2_k<<<1, 256, 0, s2>>>();
    scan3_k<<<NB_SCAN, 256, 0, s2>>>();
    fill_k<<<eb, 256, 0, s2>>>(ei);
    cudaEventRecord(evJoin, s2);

    gemm_k<true, false, false, true><<<dim3(HC / 64, mb), 256>>>(
        x, nullptr, nullptr, W0, nullptr, as0, ad0, h, NN, 128, HC);

    // ---- join: gather needs CSR + GEMM0 ----
    cudaStreamWaitEvent(0, evJoin, 0);

    gather_k<true><<<gb, 256>>>(h, x1, b0, gamma0, beta0);

    // ---- layer 1 ----
    gemm_k<true, false, false, true><<<dim3(HC / 64, mb), 256>>>(
        x1, nullptr, nullptr, W1, nullptr, as1, ad1, h, NN, HC, HC);
    gather_k<false><<<gb, 256>>>(h, acc, nullptr, nullptr, nullptr);

    // ---- JK-max + final projection: out = max(x1, acc + b1) @ Wf + bf ----
    gemm_k<false, true, true, false><<<dim3(1, mb), 256>>>(
        x1, acc, b1, Wf, bf, nullptr, nullptr, out, NN, HC, 64);
}

// round 6
// speedup vs baseline: 3.7231x; 1.4415x over previous
#include <cuda_runtime.h>
#include <cuda_fp16.h>
#include <math.h>

#define NN 50000
#define NE 800000
#define NET (NE + NN)       // edges + self loops = 850000
#define HC 256              // H*C
#define NH 4
#define CC 64
#define NB_SCAN 196         // ceil(NN/256)

// ---------------- scratch (static device globals; no allocs) ----------------
__device__ __align__(16) __half g_h[NN * HC];     // transformed features (fp16, per layer)
__device__ __align__(16) float g_x1[NN * HC];     // layer-0 activated output
__device__ __align__(16) float g_acc[NN * HC];    // layer-1 aggregation output
__device__ __align__(16) float g_asrc[NN * NH];
__device__ __align__(16) float g_adst[NN * NH];
__device__ int g_deg[NN];
__device__ int g_off[NN + 1];
__device__ int g_cur[NN];
__device__ int g_part[NB_SCAN];
__device__ int g_adj[NET];                        // src ids grouped by dst
__device__ int g_is64;

// ---------------- utility ----------------
__global__ void zeroi_k(int* p, int n) {
    int i = blockIdx.x * blockDim.x + threadIdx.x;
    if (i < n) p[i] = 0;
}

__global__ void detect_k(const int* ei32) {
    if (threadIdx.x == 0 && blockIdx.x == 0) {
        int ok = 1;
        #pragma unroll
        for (int k = 0; k < 64; k++)
            if (ei32[2 * k + 1] != 0) ok = 0;
        g_is64 = ok;
    }
}

__device__ __forceinline__ void edge_sd(const void* ei, int e, int& s, int& d) {
    if (e >= NE) { s = d = e - NE; return; }
    if (g_is64) {
        const long long* p = (const long long*)ei;
        s = (int)p[e];
        d = (int)p[NE + e];
    } else {
        const int* p = (const int*)ei;
        s = p[e];
        d = p[NE + e];
    }
}

// ---------------- CSR build ----------------
__global__ void hist_k(const void* __restrict__ ei) {
    int e = blockIdx.x * blockDim.x + threadIdx.x;
    if (e >= NET) return;
    int s, d;
    edge_sd(ei, e, s, d);
    atomicAdd(&g_deg[d], 1);
}

__global__ void scan1_k() {
    __shared__ int sh[256];
    int i = blockIdx.x * 256 + threadIdx.x;
    int v = (i < NN) ? g_deg[i] : 0;
    sh[threadIdx.x] = v; __syncthreads();
    for (int o = 128; o; o >>= 1) {
        if (threadIdx.x < o) sh[threadIdx.x] += sh[threadIdx.x + o];
        __syncthreads();
    }
    if (threadIdx.x == 0) g_part[blockIdx.x] = sh[0];
}

__global__ void scan2_k() {
    __shared__ int sh[256];
    int t = threadIdx.x;
    int v = (t < NB_SCAN) ? g_part[t] : 0;
    sh[t] = v; __syncthreads();
    for (int o = 1; o < 256; o <<= 1) {
        int x = (t >= o) ? sh[t - o] : 0;
        __syncthreads();
        sh[t] += x;
        __syncthreads();
    }
    if (t < NB_SCAN) g_part[t] = sh[t] - v;
}

__global__ void scan3_k() {
    __shared__ int sh[256];
    int t = threadIdx.x;
    int i = blockIdx.x * 256 + t;
    int v = (i < NN) ? g_deg[i] : 0;
    sh[t] = v; __syncthreads();
    for (int o = 1; o < 256; o <<= 1) {
        int x = (t >= o) ? sh[t - o] : 0;
        __syncthreads();
        sh[t] += x;
        __syncthreads();
    }
    if (i < NN) {
        int off = g_part[blockIdx.x] + sh[t] - v;
        g_off[i] = off;
        g_cur[i] = off;
        if (i == NN - 1) g_off[NN] = off + v;
    }
}

__global__ void fill_k(const void* __restrict__ ei) {
    int e = blockIdx.x * blockDim.x + threadIdx.x;
    if (e >= NET) return;
    int s, d;
    edge_sd(ei, e, s, d);
    int p = atomicAdd(&g_cur[d], 1);
    g_adj[p] = s;
}

// ---------------- tensor-core GEMM (fp16 HMMA, fp32 accum) ----------------
// C[M,Nc] = A[M,K] @ B[K,Nc]; A,B fp32 in global, converted to fp16 in smem.
// Output: fp16 into Cv. Also computes per-row alpha dots (head = blockIdx.x).
// BM=128, BN=64, BK=32, 256 threads = 8 warps (4 in M x 2 in N).
#define APAD 40
#define BPAD 72
__device__ __forceinline__ unsigned su32(const void* p) {
    return (unsigned)__cvta_generic_to_shared(p);
}
__device__ __forceinline__ void ldm_x4(unsigned addr, unsigned& r0, unsigned& r1,
                                       unsigned& r2, unsigned& r3) {
    asm volatile("ldmatrix.sync.aligned.m8n8.x4.shared.b16 {%0,%1,%2,%3},[%4];"
                 : "=r"(r0), "=r"(r1), "=r"(r2), "=r"(r3) : "r"(addr));
}
__device__ __forceinline__ void ldm_x4t(unsigned addr, unsigned& r0, unsigned& r1,
                                        unsigned& r2, unsigned& r3) {
    asm volatile("ldmatrix.sync.aligned.m8n8.x4.trans.shared.b16 {%0,%1,%2,%3},[%4];"
                 : "=r"(r0), "=r"(r1), "=r"(r2), "=r"(r3) : "r"(addr));
}
__device__ __forceinline__ void mma16816(float& d0, float& d1, float& d2, float& d3,
                                         unsigned a0, unsigned a1, unsigned a2, unsigned a3,
                                         unsigned b0, unsigned b1) {
    asm volatile(
        "mma.sync.aligned.m16n8k16.row.col.f32.f16.f16.f32 "
        "{%0,%1,%2,%3},{%4,%5,%6,%7},{%8,%9},{%0,%1,%2,%3};"
        : "+f"(d0), "+f"(d1), "+f"(d2), "+f"(d3)
        : "r"(a0), "r"(a1), "r"(a2), "r"(a3), "r"(b0), "r"(b1));
}

__global__ __launch_bounds__(256) void gemm16_k(
    const float* __restrict__ A, const float* __restrict__ B,
    const float* __restrict__ aS, const float* __restrict__ aD,
    __half* __restrict__ C, int M, int K, int Nc)
{
    __shared__ __half As[128][APAD];
    __shared__ __half Bs[32][BPAD];
    __shared__ float sPs[128];
    __shared__ float sPd[128];

    const int tid = threadIdx.x;
    const int lane = tid & 31;
    const int warp = tid >> 5;
    const int wm = warp & 3;       // 0..3 -> 32 rows each
    const int wn = warp >> 2;      // 0..1 -> 32 cols each
    const int m0 = blockIdx.y * 128;
    const int n0 = blockIdx.x * 64;

    float acc[2][4][4];
    #pragma unroll
    for (int mt = 0; mt < 2; mt++)
        #pragma unroll
        for (int nt = 0; nt < 4; nt++)
            #pragma unroll
            for (int r = 0; r < 4; r++) acc[mt][nt][r] = 0.f;

    if (tid < 128) { sPs[tid] = 0.f; sPd[tid] = 0.f; }

    for (int kt = 0; kt < K; kt += 32) {
        // A tile: 128x32 fp32 -> fp16. 1024 float4 chunks, 4 per thread.
        #pragma unroll
        for (int i = 0; i < 4; i++) {
            int q = tid + i * 256;             // 0..1023
            int row = q >> 3;
            int ks = (q & 7) * 4;
            float4 v = make_float4(0.f, 0.f, 0.f, 0.f);
            if (m0 + row < M)
                v = *(const float4*)(A + (size_t)(m0 + row) * K + kt + ks);
            __half2 p0 = __floats2half2_rn(v.x, v.y);
            __half2 p1 = __floats2half2_rn(v.z, v.w);
            *(__half2*)&As[row][ks] = p0;
            *(__half2*)&As[row][ks + 2] = p1;
        }
        // B tile: 32x64 fp32 -> fp16. 512 float4 chunks, 2 per thread.
        #pragma unroll
        for (int i = 0; i < 2; i++) {
            int q = tid + i * 256;             // 0..511
            int kr = q >> 4;
            int ns = (q & 15) * 4;
            float4 v = *(const float4*)(B + (size_t)(kt + kr) * Nc + n0 + ns);
            __half2 p0 = __floats2half2_rn(v.x, v.y);
            __half2 p1 = __floats2half2_rn(v.z, v.w);
            *(__half2*)&Bs[kr][ns] = p0;
            *(__half2*)&Bs[kr][ns + 2] = p1;
        }
        __syncthreads();

        #pragma unroll
        for (int kg = 0; kg < 2; kg++) {
            unsigned a[2][4], bq[2][4];
            #pragma unroll
            for (int mt = 0; mt < 2; mt++) {
                unsigned ad = su32(&As[wm * 32 + mt * 16 + (lane & 15)]
                                      [kg * 16 + (lane >> 4) * 8]);
                ldm_x4(ad, a[mt][0], a[mt][1], a[mt][2], a[mt][3]);
            }
            #pragma unroll
            for (int np = 0; np < 2; np++) {
                unsigned bd = su32(&Bs[kg * 16 + (lane & 15)]
                                      [wn * 32 + np * 16 + (lane >> 4) * 8]);
                ldm_x4t(bd, bq[np][0], bq[np][1], bq[np][2], bq[np][3]);
            }
            #pragma unroll
            for (int mt = 0; mt < 2; mt++)
                #pragma unroll
                for (int nt = 0; nt < 4; nt++) {
                    unsigned b0 = bq[nt >> 1][(nt & 1) * 2];
                    unsigned b1 = bq[nt >> 1][(nt & 1) * 2 + 1];
                    mma16816(acc[mt][nt][0], acc[mt][nt][1],
                             acc[mt][nt][2], acc[mt][nt][3],
                             a[mt][0], a[mt][1], a[mt][2], a[mt][3], b0, b1);
                }
        }
        __syncthreads();
    }

    // ---- store C (fp16) ----
    #pragma unroll
    for (int mt = 0; mt < 2; mt++) {
        int row0 = m0 + wm * 32 + mt * 16 + (lane >> 2);
        #pragma unroll
        for (int nt = 0; nt < 4; nt++) {
            int col = n0 + wn * 32 + nt * 8 + 2 * (lane & 3);
            if (row0 < M)
                *(__half2*)(C + (size_t)row0 * Nc + col) =
                    __floats2half2_rn(acc[mt][nt][0], acc[mt][nt][1]);
            if (row0 + 8 < M)
                *(__half2*)(C + (size_t)(row0 + 8) * Nc + col) =
                    __floats2half2_rn(acc[mt][nt][2], acc[mt][nt][3]);
        }
    }

    // ---- alpha dots: per-row <c, aS>, <c, aD> over this head's 64 cols ----
    #pragma unroll
    for (int mt = 0; mt < 2; mt++) {
        float psg = 0.f, psg8 = 0.f, pdg = 0.f, pdg8 = 0.f;
        #pragma unroll
        for (int nt = 0; nt < 4; nt++) {
            int col = n0 + wn * 32 + nt * 8 + 2 * (lane & 3);
            float2 sv = *(const float2*)(aS + col);
            float2 dv = *(const float2*)(aD + col);
            psg  += acc[mt][nt][0] * sv.x + acc[mt][nt][1] * sv.y;
            psg8 += acc[mt][nt][2] * sv.x + acc[mt][nt][3] * sv.y;
            pdg  += acc[mt][nt][0] * dv.x + acc[mt][nt][1] * dv.y;
            pdg8 += acc[mt][nt][2] * dv.x + acc[mt][nt][3] * dv.y;
        }
        #pragma unroll
        for (int o = 1; o <= 2; o <<= 1) {
            psg  += __shfl_xor_sync(0xffffffffu, psg, o);
            psg8 += __shfl_xor_sync(0xffffffffu, psg8, o);
            pdg  += __shfl_xor_sync(0xffffffffu, pdg, o);
            pdg8 += __shfl_xor_sync(0xffffffffu, pdg8, o);
        }
        if ((lane & 3) == 0) {
            int rl = wm * 32 + mt * 16 + (lane >> 2);
            atomicAdd(&sPs[rl], psg);
            atomicAdd(&sPs[rl + 8], psg8);
            atomicAdd(&sPd[rl], pdg);
            atomicAdd(&sPd[rl + 8], pdg8);
        }
    }
    __syncthreads();
    if (tid < 128) {
        int row = m0 + tid;
        if (row < M) {
            int head = blockIdx.x;   // BN=64 = one head
            g_asrc[row * 4 + head] = sPs[tid];
            g_adst[row * 4 + head] = sPd[tid];
        }
    }
}

// ---------------- fp32 SIMT GEMM (final projection w/ JK-max fusion) ----------------
__global__ __launch_bounds__(256) void gemmf_k(
    const float* __restrict__ A, const float* __restrict__ A2,
    const float* __restrict__ ab, const float* __restrict__ B,
    const float* __restrict__ bias, float* __restrict__ C,
    int M, int K, int Nc)
{
    __shared__ float As[16][132];
    __shared__ float Bs[16][64];
    const int tid = threadIdx.x;
    const int m0 = blockIdx.y * 128;
    const int n0 = blockIdx.x * 64;
    const int ty = tid >> 4;
    const int tx = tid & 15;

    float acc[8][4];
    #pragma unroll
    for (int i = 0; i < 8; i++)
        #pragma unroll
        for (int j = 0; j < 4; j++) acc[i][j] = 0.0f;

    for (int kt = 0; kt < K; kt += 16) {
        #pragma unroll
        for (int q0 = 0; q0 < 2; q0++) {
            int q = tid + q0 * 256;
            int r = q >> 2;
            int kb = (q & 3) * 4;
            int row = m0 + r;
            float4 v = make_float4(0.f, 0.f, 0.f, 0.f);
            if (row < M) {
                v = *(const float4*)(A + (size_t)row * K + kt + kb);
                float4 v2 = *(const float4*)(A2 + (size_t)row * K + kt + kb);
                float4 bb = *(const float4*)(ab + kt + kb);
                v.x = fmaxf(v.x, v2.x + bb.x);
                v.y = fmaxf(v.y, v2.y + bb.y);
                v.z = fmaxf(v.z, v2.z + bb.z);
                v.w = fmaxf(v.w, v2.w + bb.w);
            }
            As[kb + 0][r] = v.x;
            As[kb + 1][r] = v.y;
            As[kb + 2][r] = v.z;
            As[kb + 3][r] = v.w;
        }
        {
            int r = tid >> 4;
            int n = (tid & 15) * 4;
            *(float4*)&Bs[r][n] = *(const float4*)(B + (size_t)(kt + r) * Nc + n0 + n);
        }
        __syncthreads();

        #pragma unroll
        for (int kk = 0; kk < 16; kk++) {
            float4 a0 = *(const float4*)&As[kk][ty * 8];
            float4 a1 = *(const float4*)&As[kk][ty * 8 + 4];
            float4 bv = *(const float4*)&Bs[kk][tx * 4];
            float a[8] = {a0.x, a0.y, a0.z, a0.w, a1.x, a1.y, a1.z, a1.w};
            float b[4] = {bv.x, bv.y, bv.z, bv.w};
            #pragma unroll
            for (int i = 0; i < 8; i++)
                #pragma unroll
                for (int j = 0; j < 4; j++)
                    acc[i][j] = fmaf(a[i], b[j], acc[i][j]);
        }
        __syncthreads();
    }

    float4 bv = *(const float4*)(bias + n0 + tx * 4);
    #pragma unroll
    for (int i = 0; i < 8; i++) {
        int row = m0 + ty * 8 + i;
        if (row < M) {
            float4 v = make_float4(acc[i][0] + bv.x, acc[i][1] + bv.y,
                                   acc[i][2] + bv.z, acc[i][3] + bv.w);
            *(float4*)(C + (size_t)row * Nc + n0 + tx * 4) = v;
        }
    }
}

// ---------------- fused edge-softmax + CSR gather (fp16 features) ----------------
template <bool ACT>
__global__ __launch_bounds__(256) void gather_k(
    const __half* __restrict__ h, float* __restrict__ out,
    const float* __restrict__ b0,
    const float* __restrict__ gamma,
    const float* __restrict__ beta)
{
    int node = blockIdx.x * 8 + (threadIdx.x >> 5);
    if (node >= NN) return;
    int t = threadIdx.x & 31;
    int head = t >> 3;
    int oct = t & 7;
    int p = g_off[node];
    const int end = g_off[node + 1];

    const float ad = g_adst[node * 4 + head];
    float a[8];
    #pragma unroll
    for (int i = 0; i < 8; i++) a[i] = 0.f;
    float wsum = 0.f;

    const int coff = head * 64 + oct * 8;

    for (; p + 4 <= end; p += 4) {
        int s0 = g_adj[p + 0];
        int s1 = g_adj[p + 1];
        int s2 = g_adj[p + 2];
        int s3 = g_adj[p + 3];
        float e0 = g_asrc[s0 * 4 + head] + ad;
        float e1 = g_asrc[s1 * 4 + head] + ad;
        float e2 = g_asrc[s2 * 4 + head] + ad;
        float e3 = g_asrc[s3 * 4 + head] + ad;
        uint4 r0 = *(const uint4*)(h + (size_t)s0 * HC + coff);
        uint4 r1 = *(const uint4*)(h + (size_t)s1 * HC + coff);
        uint4 r2 = *(const uint4*)(h + (size_t)s2 * HC + coff);
        uint4 r3 = *(const uint4*)(h + (size_t)s3 * HC + coff);
        e0 = e0 > 0.f ? e0 : 0.2f * e0;
        e1 = e1 > 0.f ? e1 : 0.2f * e1;
        e2 = e2 > 0.f ? e2 : 0.2f * e2;
        e3 = e3 > 0.f ? e3 : 0.2f * e3;
        float w0 = __expf(e0), w1 = __expf(e1), w2 = __expf(e2), w3 = __expf(e3);
        wsum += (w0 + w1) + (w2 + w3);
        const uint4* rr[4] = {&r0, &r1, &r2, &r3};
        float ww[4] = {w0, w1, w2, w3};
        #pragma unroll
        for (int u = 0; u < 4; u++) {
            float2 f0 = __half22float2(*(const __half2*)&rr[u]->x);
            float2 f1 = __half22float2(*(const __half2*)&rr[u]->y);
            float2 f2 = __half22float2(*(const __half2*)&rr[u]->z);
            float2 f3 = __half22float2(*(const __half2*)&rr[u]->w);
            float w = ww[u];
            a[0] = fmaf(w, f0.x, a[0]);
            a[1] = fmaf(w, f0.y, a[1]);
            a[2] = fmaf(w, f1.x, a[2]);
            a[3] = fmaf(w, f1.y, a[3]);
            a[4] = fmaf(w, f2.x, a[4]);
            a[5] = fmaf(w, f2.y, a[5]);
            a[6] = fmaf(w, f3.x, a[6]);
            a[7] = fmaf(w, f3.y, a[7]);
        }
    }
    for (; p < end; p++) {
        int s = g_adj[p];
        float e = g_asrc[s * 4 + head] + ad;
        e = e > 0.f ? e : 0.2f * e;
        float w = __expf(e);
        uint4 raw = *(const uint4*)(h + (size_t)s * HC + coff);
        float2 f0 = __half22float2(*(__half2*)&raw.x);
        float2 f1 = __half22float2(*(__half2*)&raw.y);
        float2 f2 = __half22float2(*(__half2*)&raw.z);
        float2 f3 = __half22float2(*(__half2*)&raw.w);
        a[0] = fmaf(w, f0.x, a[0]);
        a[1] = fmaf(w, f0.y, a[1]);
        a[2] = fmaf(w, f1.x, a[2]);
        a[3] = fmaf(w, f1.y, a[3]);
        a[4] = fmaf(w, f2.x, a[4]);
        a[5] = fmaf(w, f2.y, a[5]);
        a[6] = fmaf(w, f3.x, a[6]);
        a[7] = fmaf(w, f3.y, a[7]);
        wsum += w;
    }

    float inv = 1.0f / (wsum + 1e-16f);
    #pragma unroll
    for (int i = 0; i < 8; i++) a[i] *= inv;

    float* op = out + (size_t)node * HC + coff;
    if (ACT) {
        const float r = rsqrtf(1.0f + 1e-5f);
        #pragma unroll
        for (int u = 0; u < 2; u++) {
            float4 bb = *(const float4*)(b0 + coff + u * 4);
            float4 gg = *(const float4*)(gamma + coff + u * 4);
            float4 be = *(const float4*)(beta + coff + u * 4);
            float v0 = (a[u * 4 + 0] + bb.x) * (gg.x * r) + be.x;
            float v1 = (a[u * 4 + 1] + bb.y) * (gg.y * r) + be.y;
            float v2 = (a[u * 4 + 2] + bb.z) * (gg.z * r) + be.z;
            float v3 = (a[u * 4 + 3] + bb.w) * (gg.w * r) + be.w;
            float4 o;
            o.x = v0 > 0.f ? v0 : expm1f(v0);
            o.y = v1 > 0.f ? v1 : expm1f(v1);
            o.z = v2 > 0.f ? v2 : expm1f(v2);
            o.w = v3 > 0.f ? v3 : expm1f(v3);
            *(float4*)(op + u * 4) = o;
        }
    } else {
        *(float4*)op = make_float4(a[0], a[1], a[2], a[3]);
        *(float4*)(op + 4) = make_float4(a[4], a[5], a[6], a[7]);
    }
}

// ---------------- launch ----------------
extern "C" void kernel_launch(void* const* d_in, const int* in_sizes, int n_in,
                              void* d_out, int out_size)
{
    const float* x      = (const float*)d_in[0];
    const void*  ei     = d_in[1];
    const float* W0     = (const float*)d_in[2];
    const float* as0    = (const float*)d_in[3];
    const float* ad0    = (const float*)d_in[4];
    const float* b0     = (const float*)d_in[5];
    const float* gamma0 = (const float*)d_in[6];
    const float* beta0  = (const float*)d_in[7];
    const float* W1     = (const float*)d_in[8];
    const float* as1    = (const float*)d_in[9];
    const float* ad1    = (const float*)d_in[10];
    const float* b1     = (const float*)d_in[11];
    const float* Wf     = (const float*)d_in[12];
    const float* bf     = (const float*)d_in[13];
    float* out = (float*)d_out;

    __half* h;
    float *x1, *acc;
    int* deg;
    cudaGetSymbolAddress((void**)&h,   g_h);
    cudaGetSymbolAddress((void**)&x1,  g_x1);
    cudaGetSymbolAddress((void**)&acc, g_acc);
    cudaGetSymbolAddress((void**)&deg, g_deg);

    static cudaStream_t s2 = nullptr;
    static cudaEvent_t evFork = nullptr, evJoin = nullptr;
    if (s2 == nullptr) {
        cudaStreamCreateWithFlags(&s2, cudaStreamNonBlocking);
        cudaEventCreateWithFlags(&evFork, cudaEventDisableTiming);
        cudaEventCreateWithFlags(&evJoin, cudaEventDisableTiming);
    }

    const int mb = (NN + 127) / 128;
    const int eb = (NET + 255) / 256;
    const int gb = (NN + 7) / 8;

    // ---- fork: CSR build on s2, concurrent with layer-0 GEMM ----
    cudaEventRecord(evFork, 0);
    cudaStreamWaitEvent(s2, evFork, 0);

    detect_k<<<1, 32, 0, s2>>>((const int*)ei);
    zeroi_k<<<(NN + 255) / 256, 256, 0, s2>>>(deg, NN);
    hist_k<<<eb, 256, 0, s2>>>(ei);
    scan1_k<<<NB_SCAN, 256, 0, s2>>>();
    scan2_k<<<1, 256, 0, s2>>>();
    scan3_k<<<NB_SCAN, 256, 0, s2>>>();
    fill_k<<<eb, 256, 0, s2>>>(ei);
    cudaEventRecord(evJoin, s2);

    gemm16_k<<<dim3(HC / 64, mb), 256>>>(x, W0, as0, ad0, h, NN, 128, HC);

    cudaStreamWaitEvent(0, evJoin, 0);

    gather_k<true><<<gb, 256>>>(h, x1, b0, gamma0, beta0);

    // ---- layer 1 ----
    gemm16_k<<<dim3(HC / 64, mb), 256>>>(x1, W1, as1, ad1, h, NN, HC, HC);
    gather_k<false><<<gb, 256>>>(h, acc, nullptr, nullptr, nullptr);

    // ---- JK-max + final projection: out = max(x1, acc + b1) @ Wf + bf ----
    gemmf_k<<<dim3(1, mb), 256>>>(x1, acc, b1, Wf, bf, out, NN, HC, 64);
}

// round 7
// speedup vs baseline: 3.8039x; 1.0217x over previous
#include <cuda_runtime.h>
#include <cuda_fp16.h>
#include <math.h>

#define NN 50000
#define NE 800000
#define NET (NE + NN)       // edges + self loops = 850000
#define HC 256              // H*C
#define NH 4
#define CC 64
#define NB_SCAN 196         // ceil(NN/256)

// ---------------- scratch (static device globals; no allocs) ----------------
__device__ __align__(16) __half g_h[NN * HC];     // transformed features (fp16, per layer)
__device__ __align__(16) float g_x1[NN * HC];     // layer-0 activated output
__device__ __align__(16) float g_acc[NN * HC];    // layer-1 aggregation output
__device__ __align__(16) float g_asrc[NN * NH];
__device__ __align__(16) float g_adst[NN * NH];
__device__ int g_deg[NN];
__device__ int g_off[NN + 1];
__device__ int g_cur[NN];
__device__ int g_part[NB_SCAN];
__device__ int g_adj[NET];                        // src ids grouped by dst
__device__ int g_is64;

// ---------------- utility ----------------
__global__ void zeroi_k(int* p, int n) {
    int i = blockIdx.x * blockDim.x + threadIdx.x;
    if (i < n) p[i] = 0;
}

__global__ void detect_k(const int* ei32) {
    if (threadIdx.x == 0 && blockIdx.x == 0) {
        int ok = 1;
        #pragma unroll
        for (int k = 0; k < 64; k++)
            if (ei32[2 * k + 1] != 0) ok = 0;
        g_is64 = ok;
    }
}

__device__ __forceinline__ void edge_sd(const void* ei, int e, int& s, int& d) {
    if (e >= NE) { s = d = e - NE; return; }
    if (g_is64) {
        const long long* p = (const long long*)ei;
        s = (int)p[e];
        d = (int)p[NE + e];
    } else {
        const int* p = (const int*)ei;
        s = p[e];
        d = p[NE + e];
    }
}

// ---------------- CSR build ----------------
__global__ void hist_k(const void* __restrict__ ei) {
    int e = blockIdx.x * blockDim.x + threadIdx.x;
    if (e >= NET) return;
    int s, d;
    edge_sd(ei, e, s, d);
    atomicAdd(&g_deg[d], 1);
}

__global__ void scan1_k() {
    __shared__ int sh[256];
    int i = blockIdx.x * 256 + threadIdx.x;
    int v = (i < NN) ? g_deg[i] : 0;
    sh[threadIdx.x] = v; __syncthreads();
    for (int o = 128; o; o >>= 1) {
        if (threadIdx.x < o) sh[threadIdx.x] += sh[threadIdx.x + o];
        __syncthreads();
    }
    if (threadIdx.x == 0) g_part[blockIdx.x] = sh[0];
}

__global__ void scan2_k() {
    __shared__ int sh[256];
    int t = threadIdx.x;
    int v = (t < NB_SCAN) ? g_part[t] : 0;
    sh[t] = v; __syncthreads();
    for (int o = 1; o < 256; o <<= 1) {
        int x = (t >= o) ? sh[t - o] : 0;
        __syncthreads();
        sh[t] += x;
        __syncthreads();
    }
    if (t < NB_SCAN) g_part[t] = sh[t] - v;
}

__global__ void scan3_k() {
    __shared__ int sh[256];
    int t = threadIdx.x;
    int i = blockIdx.x * 256 + t;
    int v = (i < NN) ? g_deg[i] : 0;
    sh[t] = v; __syncthreads();
    for (int o = 1; o < 256; o <<= 1) {
        int x = (t >= o) ? sh[t - o] : 0;
        __syncthreads();
        sh[t] += x;
        __syncthreads();
    }
    if (i < NN) {
        int off = g_part[blockIdx.x] + sh[t] - v;
        g_off[i] = off;
        g_cur[i] = off;
        if (i == NN - 1) g_off[NN] = off + v;
    }
}

__global__ void fill_k(const void* __restrict__ ei) {
    int e = blockIdx.x * blockDim.x + threadIdx.x;
    if (e >= NET) return;
    int s, d;
    edge_sd(ei, e, s, d);
    int p = atomicAdd(&g_cur[d], 1);
    g_adj[p] = s;
}

// ---------------- tensor-core GEMM (fp16 HMMA, fp32 accum) ----------------
// C[M,Nc] = A[M,K] @ B[K,Nc]; A,B fp32 in global, converted fp16 in smem.
// ALPHA: fp16 output + per-row alpha dots (head = blockIdx.x).
// FMAX:  A-element = max(A, A2 + ab); fp32 output with +bias (final projection).
// BM=128, BN=64, BK=32, 256 threads = 8 warps (4 in M x 2 in N).
// Register-staged prefetch of the next K-tile overlaps global latency with MMA.
#define APAD 40
#define BPAD 72
__device__ __forceinline__ unsigned su32(const void* p) {
    return (unsigned)__cvta_generic_to_shared(p);
}
__device__ __forceinline__ void ldm_x4(unsigned addr, unsigned& r0, unsigned& r1,
                                       unsigned& r2, unsigned& r3) {
    asm volatile("ldmatrix.sync.aligned.m8n8.x4.shared.b16 {%0,%1,%2,%3},[%4];"
                 : "=r"(r0), "=r"(r1), "=r"(r2), "=r"(r3) : "r"(addr));
}
__device__ __forceinline__ void ldm_x4t(unsigned addr, unsigned& r0, unsigned& r1,
                                        unsigned& r2, unsigned& r3) {
    asm volatile("ldmatrix.sync.aligned.m8n8.x4.trans.shared.b16 {%0,%1,%2,%3},[%4];"
                 : "=r"(r0), "=r"(r1), "=r"(r2), "=r"(r3) : "r"(addr));
}
__device__ __forceinline__ void mma16816(float& d0, float& d1, float& d2, float& d3,
                                         unsigned a0, unsigned a1, unsigned a2, unsigned a3,
                                         unsigned b0, unsigned b1) {
    asm volatile(
        "mma.sync.aligned.m16n8k16.row.col.f32.f16.f16.f32 "
        "{%0,%1,%2,%3},{%4,%5,%6,%7},{%8,%9},{%0,%1,%2,%3};"
        : "+f"(d0), "+f"(d1), "+f"(d2), "+f"(d3)
        : "r"(a0), "r"(a1), "r"(a2), "r"(a3), "r"(b0), "r"(b1));
}

template <bool ALPHA, bool FMAX>
__global__ __launch_bounds__(256) void gemm16_k(
    const float* __restrict__ A, const float* __restrict__ A2,
    const float* __restrict__ ab, const float* __restrict__ B,
    const float* __restrict__ bias,
    const float* __restrict__ aS, const float* __restrict__ aD,
    void* __restrict__ Cv, int M, int K, int Nc)
{
    __shared__ __half As[128][APAD];
    __shared__ __half Bs[32][BPAD];
    __shared__ float sPs[128];
    __shared__ float sPd[128];

    const int tid = threadIdx.x;
    const int lane = tid & 31;
    const int warp = tid >> 5;
    const int wm = warp & 3;
    const int wn = warp >> 2;
    const int m0 = blockIdx.y * 128;
    const int n0 = blockIdx.x * 64;

    float acc[2][4][4];
    #pragma unroll
    for (int mt = 0; mt < 2; mt++)
        #pragma unroll
        for (int nt = 0; nt < 4; nt++)
            #pragma unroll
            for (int r = 0; r < 4; r++) acc[mt][nt][r] = 0.f;

    if (ALPHA && tid < 128) { sPs[tid] = 0.f; sPd[tid] = 0.f; }

    float4 ra[4], rb[2], ran[4], rbn[2];

    // tile loader into registers (A-side applies FMAX fusion at load)
    auto load_frag = [&](int kt, float4 (&la)[4], float4 (&lb)[2]) {
        #pragma unroll
        for (int i = 0; i < 4; i++) {
            int q = tid + i * 256;
            int row = q >> 3;
            int ks = (q & 7) * 4;
            float4 v = make_float4(0.f, 0.f, 0.f, 0.f);
            if (m0 + row < M) {
                v = *(const float4*)(A + (size_t)(m0 + row) * K + kt + ks);
                if (FMAX) {
                    float4 v2 = *(const float4*)(A2 + (size_t)(m0 + row) * K + kt + ks);
                    float4 bb = *(const float4*)(ab + kt + ks);
                    v.x = fmaxf(v.x, v2.x + bb.x);
                    v.y = fmaxf(v.y, v2.y + bb.y);
                    v.z = fmaxf(v.z, v2.z + bb.z);
                    v.w = fmaxf(v.w, v2.w + bb.w);
                }
            }
            la[i] = v;
        }
        #pragma unroll
        for (int i = 0; i < 2; i++) {
            int q = tid + i * 256;
            int kr = q >> 4;
            int ns = (q & 15) * 4;
            lb[i] = *(const float4*)(B + (size_t)(kt + kr) * Nc + n0 + ns);
        }
    };
    auto store_frag = [&](const float4 (&la)[4], const float4 (&lb)[2]) {
        #pragma unroll
        for (int i = 0; i < 4; i++) {
            int q = tid + i * 256;
            int row = q >> 3;
            int ks = (q & 7) * 4;
            *(__half2*)&As[row][ks]     = __floats2half2_rn(la[i].x, la[i].y);
            *(__half2*)&As[row][ks + 2] = __floats2half2_rn(la[i].z, la[i].w);
        }
        #pragma unroll
        for (int i = 0; i < 2; i++) {
            int q = tid + i * 256;
            int kr = q >> 4;
            int ns = (q & 15) * 4;
            *(__half2*)&Bs[kr][ns]     = __floats2half2_rn(lb[i].x, lb[i].y);
            *(__half2*)&Bs[kr][ns + 2] = __floats2half2_rn(lb[i].z, lb[i].w);
        }
    };

    load_frag(0, ra, rb);

    for (int kt = 0; kt < K; kt += 32) {
        store_frag(ra, rb);
        __syncthreads();

        // prefetch next tile (overlaps with ldmatrix/MMA below)
        if (kt + 32 < K) load_frag(kt + 32, ran, rbn);

        #pragma unroll
        for (int kg = 0; kg < 2; kg++) {
            unsigned a[2][4], bq[2][4];
            #pragma unroll
            for (int mt = 0; mt < 2; mt++) {
                unsigned ad = su32(&As[wm * 32 + mt * 16 + (lane & 15)]
                                      [kg * 16 + (lane >> 4) * 8]);
                ldm_x4(ad, a[mt][0], a[mt][1], a[mt][2], a[mt][3]);
            }
            #pragma unroll
            for (int np = 0; np < 2; np++) {
                unsigned bd = su32(&Bs[kg * 16 + (lane & 15)]
                                      [wn * 32 + np * 16 + (lane >> 4) * 8]);
                ldm_x4t(bd, bq[np][0], bq[np][1], bq[np][2], bq[np][3]);
            }
            #pragma unroll
            for (int mt = 0; mt < 2; mt++)
                #pragma unroll
                for (int nt = 0; nt < 4; nt++) {
                    unsigned b0 = bq[nt >> 1][(nt & 1) * 2];
                    unsigned b1 = bq[nt >> 1][(nt & 1) * 2 + 1];
                    mma16816(acc[mt][nt][0], acc[mt][nt][1],
                             acc[mt][nt][2], acc[mt][nt][3],
                             a[mt][0], a[mt][1], a[mt][2], a[mt][3], b0, b1);
                }
        }
        __syncthreads();

        #pragma unroll
        for (int i = 0; i < 4; i++) ra[i] = ran[i];
        #pragma unroll
        for (int i = 0; i < 2; i++) rb[i] = rbn[i];
    }

    // ---- store C ----
    #pragma unroll
    for (int mt = 0; mt < 2; mt++) {
        int row0 = m0 + wm * 32 + mt * 16 + (lane >> 2);
        #pragma unroll
        for (int nt = 0; nt < 4; nt++) {
            int col = n0 + wn * 32 + nt * 8 + 2 * (lane & 3);
            if (ALPHA) {
                __half* C = (__half*)Cv;
                if (row0 < M)
                    *(__half2*)(C + (size_t)row0 * Nc + col) =
                        __floats2half2_rn(acc[mt][nt][0], acc[mt][nt][1]);
                if (row0 + 8 < M)
                    *(__half2*)(C + (size_t)(row0 + 8) * Nc + col) =
                        __floats2half2_rn(acc[mt][nt][2], acc[mt][nt][3]);
            } else {
                float* C = (float*)Cv;
                float2 bv = *(const float2*)(bias + col);
                if (row0 < M) {
                    float2 v = make_float2(acc[mt][nt][0] + bv.x, acc[mt][nt][1] + bv.y);
                    *(float2*)(C + (size_t)row0 * Nc + col) = v;
                }
                if (row0 + 8 < M) {
                    float2 v = make_float2(acc[mt][nt][2] + bv.x, acc[mt][nt][3] + bv.y);
                    *(float2*)(C + (size_t)(row0 + 8) * Nc + col) = v;
                }
            }
        }
    }

    if (ALPHA) {
        // ---- alpha dots: per-row <c, aS>, <c, aD> over this head's 64 cols ----
        #pragma unroll
        for (int mt = 0; mt < 2; mt++) {
            float psg = 0.f, psg8 = 0.f, pdg = 0.f, pdg8 = 0.f;
            #pragma unroll
            for (int nt = 0; nt < 4; nt++) {
                int col = n0 + wn * 32 + nt * 8 + 2 * (lane & 3);
                float2 sv = *(const float2*)(aS + col);
                float2 dv = *(const float2*)(aD + col);
                psg  += acc[mt][nt][0] * sv.x + acc[mt][nt][1] * sv.y;
                psg8 += acc[mt][nt][2] * sv.x + acc[mt][nt][3] * sv.y;
                pdg  += acc[mt][nt][0] * dv.x + acc[mt][nt][1] * dv.y;
                pdg8 += acc[mt][nt][2] * dv.x + acc[mt][nt][3] * dv.y;
            }
            #pragma unroll
            for (int o = 1; o <= 2; o <<= 1) {
                psg  += __shfl_xor_sync(0xffffffffu, psg, o);
                psg8 += __shfl_xor_sync(0xffffffffu, psg8, o);
                pdg  += __shfl_xor_sync(0xffffffffu, pdg, o);
                pdg8 += __shfl_xor_sync(0xffffffffu, pdg8, o);
            }
            if ((lane & 3) == 0) {
                int rl = wm * 32 + mt * 16 + (lane >> 2);
                atomicAdd(&sPs[rl], psg);
                atomicAdd(&sPs[rl + 8], psg8);
                atomicAdd(&sPd[rl], pdg);
                atomicAdd(&sPd[rl + 8], pdg8);
            }
        }
        __syncthreads();
        if (tid < 128) {
            int row = m0 + tid;
            if (row < M) {
                int head = blockIdx.x;
                g_asrc[row * 4 + head] = sPs[tid];
                g_adst[row * 4 + head] = sPd[tid];
            }
        }
    }
}

// ---------------- fused edge-softmax + CSR gather (fp16 features) ----------------
template <bool ACT>
__global__ __launch_bounds__(256) void gather_k(
    const __half* __restrict__ h, float* __restrict__ out,
    const float* __restrict__ b0,
    const float* __restrict__ gamma,
    const float* __restrict__ beta)
{
    int node = blockIdx.x * 8 + (threadIdx.x >> 5);
    if (node >= NN) return;
    int t = threadIdx.x & 31;
    int head = t >> 3;
    int oct = t & 7;
    int p = g_off[node];
    const int end = g_off[node + 1];

    const float ad = g_adst[node * 4 + head];
    float a[8];
    #pragma unroll
    for (int i = 0; i < 8; i++) a[i] = 0.f;
    float wsum = 0.f;

    const int coff = head * 64 + oct * 8;

    for (; p + 4 <= end; p += 4) {
        int s0 = g_adj[p + 0];
        int s1 = g_adj[p + 1];
        int s2 = g_adj[p + 2];
        int s3 = g_adj[p + 3];
        float e0 = g_asrc[s0 * 4 + head] + ad;
        float e1 = g_asrc[s1 * 4 + head] + ad;
        float e2 = g_asrc[s2 * 4 + head] + ad;
        float e3 = g_asrc[s3 * 4 + head] + ad;
        uint4 r0 = __ldcg((const uint4*)(h + (size_t)s0 * HC + coff));
        uint4 r1 = __ldcg((const uint4*)(h + (size_t)s1 * HC + coff));
        uint4 r2 = __ldcg((const uint4*)(h + (size_t)s2 * HC + coff));
        uint4 r3 = __ldcg((const uint4*)(h + (size_t)s3 * HC + coff));
        e0 = e0 > 0.f ? e0 : 0.2f * e0;
        e1 = e1 > 0.f ? e1 : 0.2f * e1;
        e2 = e2 > 0.f ? e2 : 0.2f * e2;
        e3 = e3 > 0.f ? e3 : 0.2f * e3;
        float w0 = __expf(e0), w1 = __expf(e1), w2 = __expf(e2), w3 = __expf(e3);
        wsum += (w0 + w1) + (w2 + w3);
        const uint4* rr[4] = {&r0, &r1, &r2, &r3};
        float ww[4] = {w0, w1, w2, w3};
        #pragma unroll
        for (int u = 0; u < 4; u++) {
            float2 f0 = __half22float2(*(const __half2*)&rr[u]->x);
            float2 f1 = __half22float2(*(const __half2*)&rr[u]->y);
            float2 f2 = __half22float2(*(const __half2*)&rr[u]->z);
            float2 f3 = __half22float2(*(const __half2*)&rr[u]->w);
            float w = ww[u];
            a[0] = fmaf(w, f0.x, a[0]);
            a[1] = fmaf(w, f0.y, a[1]);
            a[2] = fmaf(w, f1.x, a[2]);
            a[3] = fmaf(w, f1.y, a[3]);
            a[4] = fmaf(w, f2.x, a[4]);
            a[5] = fmaf(w, f2.y, a[5]);
            a[6] = fmaf(w, f3.x, a[6]);
            a[7] = fmaf(w, f3.y, a[7]);
        }
    }
    for (; p < end; p++) {
        int s = g_adj[p];
        float e = g_asrc[s * 4 + head] + ad;
        e = e > 0.f ? e : 0.2f * e;
        float w = __expf(e);
        uint4 raw = __ldcg((const uint4*)(h + (size_t)s * HC + coff));
        float2 f0 = __half22float2(*(__half2*)&raw.x);
        float2 f1 = __half22float2(*(__half2*)&raw.y);
        float2 f2 = __half22float2(*(__half2*)&raw.z);
        float2 f3 = __half22float2(*(__half2*)&raw.w);
        a[0] = fmaf(w, f0.x, a[0]);
        a[1] = fmaf(w, f0.y, a[1]);
        a[2] = fmaf(w, f1.x, a[2]);
        a[3] = fmaf(w, f1.y, a[3]);
        a[4] = fmaf(w, f2.x, a[4]);
        a[5] = fmaf(w, f2.y, a[5]);
        a[6] = fmaf(w, f3.x, a[6]);
        a[7] = fmaf(w, f3.y, a[7]);
        wsum += w;
    }

    float inv = 1.0f / (wsum + 1e-16f);
    #pragma unroll
    for (int i = 0; i < 8; i++) a[i] *= inv;

    float* op = out + (size_t)node * HC + coff;
    if (ACT) {
        const float r = rsqrtf(1.0f + 1e-5f);
        #pragma unroll
        for (int u = 0; u < 2; u++) {
            float4 bb = *(const float4*)(b0 + coff + u * 4);
            float4 gg = *(const float4*)(gamma + coff + u * 4);
            float4 be = *(const float4*)(beta + coff + u * 4);
            float v0 = (a[u * 4 + 0] + bb.x) * (gg.x * r) + be.x;
            float v1 = (a[u * 4 + 1] + bb.y) * (gg.y * r) + be.y;
            float v2 = (a[u * 4 + 2] + bb.z) * (gg.z * r) + be.z;
            float v3 = (a[u * 4 + 3] + bb.w) * (gg.w * r) + be.w;
            float4 o;
            o.x = v0 > 0.f ? v0 : expm1f(v0);
            o.y = v1 > 0.f ? v1 : expm1f(v1);
            o.z = v2 > 0.f ? v2 : expm1f(v2);
            o.w = v3 > 0.f ? v3 : expm1f(v3);
            *(float4*)(op + u * 4) = o;
        }
    } else {
        *(float4*)op = make_float4(a[0], a[1], a[2], a[3]);
        *(float4*)(op + 4) = make_float4(a[4], a[5], a[6], a[7]);
    }
}

// ---------------- launch ----------------
extern "C" void kernel_launch(void* const* d_in, const int* in_sizes, int n_in,
                              void* d_out, int out_size)
{
    const float* x      = (const float*)d_in[0];
    const void*  ei     = d_in[1];
    const float* W0     = (const float*)d_in[2];
    const float* as0    = (const float*)d_in[3];
    const float* ad0    = (const float*)d_in[4];
    const float* b0     = (const float*)d_in[5];
    const float* gamma0 = (const float*)d_in[6];
    const float* beta0  = (const float*)d_in[7];
    const float* W1     = (const float*)d_in[8];
    const float* as1    = (const float*)d_in[9];
    const float* ad1    = (const float*)d_in[10];
    const float* b1     = (const float*)d_in[11];
    const float* Wf     = (const float*)d_in[12];
    const float* bf     = (const float*)d_in[13];
    float* out = (float*)d_out;

    __half* h;
    float *x1, *acc;
    int* deg;
    cudaGetSymbolAddress((void**)&h,   g_h);
    cudaGetSymbolAddress((void**)&x1,  g_x1);
    cudaGetSymbolAddress((void**)&acc, g_acc);
    cudaGetSymbolAddress((void**)&deg, g_deg);

    static cudaStream_t s2 = nullptr;
    static cudaEvent_t evFork = nullptr, evJoin = nullptr;
    if (s2 == nullptr) {
        cudaStreamCreateWithFlags(&s2, cudaStreamNonBlocking);
        cudaEventCreateWithFlags(&evFork, cudaEventDisableTiming);
        cudaEventCreateWithFlags(&evJoin, cudaEventDisableTiming);
    }

    const int mb = (NN + 127) / 128;
    const int eb = (NET + 255) / 256;
    const int gb = (NN + 7) / 8;

    // ---- fork: CSR build on s2, concurrent with layer-0 GEMM ----
    cudaEventRecord(evFork, 0);
    cudaStreamWaitEvent(s2, evFork, 0);

    detect_k<<<1, 32, 0, s2>>>((const int*)ei);
    zeroi_k<<<(NN + 255) / 256, 256, 0, s2>>>(deg, NN);
    hist_k<<<eb, 256, 0, s2>>>(ei);
    scan1_k<<<NB_SCAN, 256, 0, s2>>>();
    scan2_k<<<1, 256, 0, s2>>>();
    scan3_k<<<NB_SCAN, 256, 0, s2>>>();
    fill_k<<<eb, 256, 0, s2>>>(ei);
    cudaEventRecord(evJoin, s2);

    gemm16_k<true, false><<<dim3(HC / 64, mb), 256>>>(
        x, nullptr, nullptr, W0, nullptr, as0, ad0, h, NN, 128, HC);

    cudaStreamWaitEvent(0, evJoin, 0);

    gather_k<true><<<gb, 256>>>(h, x1, b0, gamma0, beta0);

    // ---- layer 1 ----
    gemm16_k<true, false><<<dim3(HC / 64, mb), 256>>>(
        x1, nullptr, nullptr, W1, nullptr, as1, ad1, h, NN, HC, HC);
    gather_k<false><<<gb, 256>>>(h, acc, nullptr, nullptr, nullptr);

    // ---- JK-max + final projection: out = max(x1, acc + b1) @ Wf + bf ----
    gemm16_k<false, true><<<dim3(1, mb), 256>>>(
        x1, acc, b1, Wf, bf, nullptr, nullptr, out, NN, HC, 64);
}